// round 5
// baseline (speedup 1.0000x reference)
#include <cuda_runtime.h>
#include <cuda_bf16.h>
#include <math.h>

// ---------------- static problem dims ----------------
// src: (8, 128, 64, 256). Token n = (b*128 + r)*64 + c  = b*8192 + r*64 + c
// Stage1: sequences (b1 = b*128+r) of length C=64.
// Stage2: sequences (b2 = b*64 + c) of length R=128, split S=96 ctx / 32 qry.
#define NTOK 65536
#define EDIM 256

// ---------------- scratch (device globals; no allocations) ----------------
__device__ float g_x0 [(size_t)NTOK * 256];      // nan_to_num(src); later reused for MLP out
__device__ float g_qkv[(size_t)NTOK * 768];      // qkv projections (stage1, then stage2)
__device__ float g_att[(size_t)NTOK * 256];      // attention outputs (head-merged)
__device__ float g_xn [(size_t)NTOK * 256];      // after LN1
__device__ float g_y  [(size_t)NTOK * 256];      // stage1 out, then stage2 updated tokens
__device__ float g_kv2[(size_t)512 * 96 * 512];  // recomputed K,V of updated ctx (compact)
__device__ float g_z  [(size_t)NTOK * 256];      // after LN2
__device__ float g_h  [(size_t)NTOK * 1024];     // MLP hidden

// inv_freq[i] = 10000^(-i/16), i = 0..15 (hd=32, interleaved pairs)
__constant__ float c_invfreq[16] = {
  1.0f, 0.5623413251903491f, 0.31622776601683794f, 0.17782794100389228f,
  0.1f, 0.05623413251903491f, 0.031622776601683794f, 0.017782794100389228f,
  0.01f, 0.005623413251903491f, 0.0031622776601683794f, 0.0017782794100389229f,
  0.001f, 0.0005623413251903491f, 0.00031622776601683794f, 0.00017782794100389227f
};

enum { MAP_ID = 0, MAP_CTX = 1, MAP_QRY = 2 };
enum { EPI_B = 0, EPI_RES = 1, EPI_GELU = 2 };

template<int MAP>
__device__ __forceinline__ int map_row(int m) {
  if (MAP == MAP_ID) {
    return m;
  } else if (MAP == MAP_CTX) {            // m = b2*96 + r,  r in [0,96)
    int b2 = m / 96, r = m - b2 * 96;
    int b = b2 >> 6, c = b2 & 63;
    return b * 8192 + r * 64 + c;
  } else {                                 // m = b2*32 + i,  r = 96 + i
    int b2 = m >> 5, i = m & 31;
    int b = b2 >> 6, c = b2 & 63;
    return b * 8192 + (96 + i) * 64 + c;
  }
}

// ---------------- NT GEMM: C[M,N] = A[M,K] . W[N,K]^T + bias (+epilogue) ----------
// 128x128 tile, BK=8, 256 threads, 8x8 accum per thread, register prefetch.
template<int MAPA, int MAPC, int EPI>
__global__ __launch_bounds__(256, 2)
void gemm_nt(const float* __restrict__ A, const float* __restrict__ W,
             const float* __restrict__ bias, float* __restrict__ C,
             const float* __restrict__ Res, int M, int N, int K)
{
  __shared__ float As[8][128];
  __shared__ float Bs[8][128];
  const int t  = threadIdx.x;
  const int lr = t >> 1;
  const int lc = (t & 1) << 2;
  const int tx = t & 15, ty = t >> 4;
  const int mt = blockIdx.y * 128;
  const int nt = blockIdx.x * 128;

  const int arow = map_row<MAPA>(mt + lr);
  const float* Ap = A + (size_t)arow * K + lc;
  const float* Wp = W + (size_t)(nt + lr) * K + lc;

  float acc[8][8];
#pragma unroll
  for (int i = 0; i < 8; i++)
#pragma unroll
    for (int j = 0; j < 8; j++) acc[i][j] = 0.f;

  float4 av = *(const float4*)Ap;
  float4 wv = *(const float4*)Wp;
  for (int k0 = 0; k0 < K; k0 += 8) {
    As[lc+0][lr] = av.x; As[lc+1][lr] = av.y; As[lc+2][lr] = av.z; As[lc+3][lr] = av.w;
    Bs[lc+0][lr] = wv.x; Bs[lc+1][lr] = wv.y; Bs[lc+2][lr] = wv.z; Bs[lc+3][lr] = wv.w;
    __syncthreads();
    if (k0 + 8 < K) {
      av = *(const float4*)(Ap + k0 + 8);
      wv = *(const float4*)(Wp + k0 + 8);
    }
#pragma unroll
    for (int kk = 0; kk < 8; kk++) {
      float4 a0 = *(const float4*)&As[kk][ty * 8];
      float4 a1 = *(const float4*)&As[kk][ty * 8 + 4];
      float4 b0 = *(const float4*)&Bs[kk][tx * 8];
      float4 b1 = *(const float4*)&Bs[kk][tx * 8 + 4];
      float ar[8] = {a0.x,a0.y,a0.z,a0.w,a1.x,a1.y,a1.z,a1.w};
      float br[8] = {b0.x,b0.y,b0.z,b0.w,b1.x,b1.y,b1.z,b1.w};
#pragma unroll
      for (int i = 0; i < 8; i++)
#pragma unroll
        for (int j = 0; j < 8; j++)
          acc[i][j] = fmaf(ar[i], br[j], acc[i][j]);
    }
    __syncthreads();
  }

  float4 bv0 = *(const float4*)&bias[nt + tx * 8];
  float4 bv1 = *(const float4*)&bias[nt + tx * 8 + 4];
  float bl[8] = {bv0.x,bv0.y,bv0.z,bv0.w,bv1.x,bv1.y,bv1.z,bv1.w};
#pragma unroll
  for (int i = 0; i < 8; i++) {
    int crow = map_row<MAPC>(mt + ty * 8 + i);
    float* Cp = C + (size_t)crow * N + nt + tx * 8;
    float o[8];
#pragma unroll
    for (int j = 0; j < 8; j++) o[j] = acc[i][j] + bl[j];
    if (EPI == EPI_RES) {
      const float* Rp = Res + (size_t)crow * N + nt + tx * 8;
      float4 r0 = *(const float4*)Rp;
      float4 r1 = *(const float4*)(Rp + 4);
      o[0]+=r0.x; o[1]+=r0.y; o[2]+=r0.z; o[3]+=r0.w;
      o[4]+=r1.x; o[5]+=r1.y; o[6]+=r1.z; o[7]+=r1.w;
    }
    if (EPI == EPI_GELU) {
#pragma unroll
      for (int j = 0; j < 8; j++)
        o[j] = 0.5f * o[j] * (1.0f + erff(o[j] * 0.7071067811865475f));
    }
    *(float4*)Cp       = make_float4(o[0], o[1], o[2], o[3]);
    *(float4*)(Cp + 4) = make_float4(o[4], o[5], o[6], o[7]);
  }
}

// ---------------- stage-1 attention: per (b1, h), L=64, hd=32 ----------------
__global__ __launch_bounds__(256)
void att1_kernel(const float* __restrict__ qkv, float* __restrict__ out)
{
  __shared__ float Q[64][33], K[64][33], V[64][33], P[64][65];
  const int blk = blockIdx.x;
  const int b1 = blk >> 3, h = blk & 7;
  const int t = threadIdx.x;
  const size_t base = (size_t)b1 * 64 * 768 + h * 32;
#pragma unroll
  for (int i = 0; i < 8; i++) {
    int e = t + i * 256;
    int c = e >> 5, d = e & 31;
    size_t o = base + (size_t)c * 768 + d;
    Q[c][d] = qkv[o];
    K[c][d] = qkv[o + 256];
    V[c][d] = qkv[o + 512];
  }
  __syncthreads();
  const float scale = 0.17677669529663687f;   // 1/sqrt(32)
#pragma unroll
  for (int i = 0; i < 16; i++) {
    int e = t + i * 256;
    int iq = e >> 6, j = e & 63;
    float s = 0.f;
#pragma unroll
    for (int d = 0; d < 32; d++) s = fmaf(Q[iq][d], K[j][d], s);
    P[iq][j] = s * scale;
  }
  __syncthreads();
  const int w = t >> 5, lane = t & 31;
#pragma unroll
  for (int rr = 0; rr < 8; rr++) {
    int r = w * 8 + rr;
    float a = P[r][lane], b = P[r][lane + 32];
    float mx = fmaxf(a, b);
#pragma unroll
    for (int o = 16; o > 0; o >>= 1) mx = fmaxf(mx, __shfl_xor_sync(0xffffffffu, mx, o));
    float ea = __expf(a - mx), eb = __expf(b - mx);
    float sm = ea + eb;
#pragma unroll
    for (int o = 16; o > 0; o >>= 1) sm += __shfl_xor_sync(0xffffffffu, sm, o);
    float inv = 1.f / sm;
    P[r][lane] = ea * inv; P[r][lane + 32] = eb * inv;
  }
  __syncthreads();
#pragma unroll
  for (int i = 0; i < 8; i++) {
    int e = t + i * 256;
    int c = e >> 5, d = e & 31;
    float o = 0.f;
#pragma unroll
    for (int j = 0; j < 64; j++) o = fmaf(P[c][j], V[j][d], o);
    out[(size_t)(b1 * 64 + c) * 256 + h * 32 + d] = o;
  }
}

// ---------------- stage-2 ctx attention: per (b2, h, half), 48 q-rows, 96 keys ----
__global__ __launch_bounds__(256)
void att2_ctx_kernel(const float* __restrict__ qkv, const int* __restrict__ mask,
                     float* __restrict__ out)
{
  __shared__ float Q[48][33], KV[96][33], P[48][97];
  __shared__ float kbias[96];
  const int blk = blockIdx.x;
  const int half = blk & 1, h = (blk >> 1) & 7, b2 = blk >> 4;
  const int b = b2 >> 6, c = b2 & 63;
  const int t = threadIdx.x;
  const int q0 = half * 48;
  const size_t tokbase = (size_t)b * 8192 + c;

#pragma unroll
  for (int i = 0; i < 12; i++) {            // K: 96x32
    int e = t + i * 256;
    int r = e >> 5, d = e & 31;
    KV[r][d] = qkv[(tokbase + (size_t)r * 64) * 768 + 256 + h * 32 + d];
  }
#pragma unroll
  for (int i = 0; i < 6; i++) {             // Q: 48x32
    int e = t + i * 256;
    int iq = e >> 5, d = e & 31;
    Q[iq][d] = qkv[(tokbase + (size_t)(q0 + iq) * 64) * 768 + h * 32 + d];
  }
  if (t < 96) kbias[t] = (mask[b * 128 + t] > 0) ? 0.f : -1e9f;
  __syncthreads();
  for (int e = t; e < 96 * 16; e += 256) {  // RoPE K (pos r)
    int r = e >> 4, i = e & 15;
    float sn, cs; sincosf((float)r * c_invfreq[i], &sn, &cs);
    float ev = KV[r][2*i], ov = KV[r][2*i+1];
    KV[r][2*i] = ev * cs - ov * sn; KV[r][2*i+1] = ev * sn + ov * cs;
  }
  for (int e = t; e < 48 * 16; e += 256) {  // RoPE Q (pos q0+iq)
    int iq = e >> 4, i = e & 15;
    float sn, cs; sincosf((float)(q0 + iq) * c_invfreq[i], &sn, &cs);
    float ev = Q[iq][2*i], ov = Q[iq][2*i+1];
    Q[iq][2*i] = ev * cs - ov * sn; Q[iq][2*i+1] = ev * sn + ov * cs;
  }
  __syncthreads();
  const float scale = 0.17677669529663687f;
  for (int e = t; e < 48 * 96; e += 256) {
    int iq = e / 96, j = e - iq * 96;
    float s = 0.f;
#pragma unroll
    for (int d = 0; d < 32; d++) s = fmaf(Q[iq][d], KV[j][d], s);
    P[iq][j] = s * scale + kbias[j];
  }
  __syncthreads();
#pragma unroll
  for (int i = 0; i < 12; i++) {            // reuse KV smem for V
    int e = t + i * 256;
    int r = e >> 5, d = e & 31;
    KV[r][d] = qkv[(tokbase + (size_t)r * 64) * 768 + 512 + h * 32 + d];
  }
  const int w = t >> 5, lane = t & 31;
#pragma unroll
  for (int rr = 0; rr < 6; rr++) {          // softmax: 48 rows / 8 warps
    int r = w * 6 + rr;
    float x0 = P[r][lane], x1 = P[r][lane + 32], x2 = P[r][lane + 64];
    float mx = fmaxf(x0, fmaxf(x1, x2));
#pragma unroll
    for (int o = 16; o > 0; o >>= 1) mx = fmaxf(mx, __shfl_xor_sync(0xffffffffu, mx, o));
    float e0 = __expf(x0 - mx), e1 = __expf(x1 - mx), e2 = __expf(x2 - mx);
    float sm = e0 + e1 + e2;
#pragma unroll
    for (int o = 16; o > 0; o >>= 1) sm += __shfl_xor_sync(0xffffffffu, sm, o);
    float inv = 1.f / sm;
    P[r][lane] = e0 * inv; P[r][lane + 32] = e1 * inv; P[r][lane + 64] = e2 * inv;
  }
  __syncthreads();
#pragma unroll
  for (int ii = 0; ii < 6; ii++) {
    int e = t + ii * 256;
    int iq = e >> 5, d = e & 31;
    float o = 0.f;
#pragma unroll
    for (int j = 0; j < 96; j++) o = fmaf(P[iq][j], KV[j][d], o);
    out[(tokbase + (size_t)(q0 + iq) * 64) * 256 + h * 32 + d] = o;
  }
}

// ---------------- stage-2 qry attention: per (b2, h), 32 q-rows, 96 keys ----------
__global__ __launch_bounds__(256)
void att2_qry_kernel(const float* __restrict__ qkv, const float* __restrict__ kv2,
                     const int* __restrict__ mask, float* __restrict__ out)
{
  __shared__ float Q[32][33], KV[96][33], P[32][97];
  __shared__ float kbias[96];
  const int blk = blockIdx.x;
  const int h = blk & 7, b2 = blk >> 3;
  const int b = b2 >> 6, c = b2 & 63;
  const int t = threadIdx.x;
  const size_t tokbase = (size_t)b * 8192 + c;
  const size_t kvbase = (size_t)b2 * 96 * 512 + h * 32;

#pragma unroll
  for (int i = 0; i < 12; i++) {            // K2 (updated ctx)
    int e = t + i * 256;
    int r = e >> 5, d = e & 31;
    KV[r][d] = kv2[kvbase + (size_t)r * 512 + d];
  }
#pragma unroll
  for (int i = 0; i < 4; i++) {             // Q (qry tokens)
    int e = t + i * 256;
    int iq = e >> 5, d = e & 31;
    Q[iq][d] = qkv[(tokbase + (size_t)(96 + iq) * 64) * 768 + h * 32 + d];
  }
  if (t < 96) kbias[t] = (mask[b * 128 + t] > 0) ? 0.f : -1e9f;
  __syncthreads();
  for (int e = t; e < 96 * 16; e += 256) {  // RoPE K (pos r)
    int r = e >> 4, i = e & 15;
    float sn, cs; sincosf((float)r * c_invfreq[i], &sn, &cs);
    float ev = KV[r][2*i], ov = KV[r][2*i+1];
    KV[r][2*i] = ev * cs - ov * sn; KV[r][2*i+1] = ev * sn + ov * cs;
  }
  for (int e = t; e < 32 * 16; e += 256) {  // RoPE Q (pos 96+iq)
    int iq = e >> 4, i = e & 15;
    float sn, cs; sincosf((float)(96 + iq) * c_invfreq[i], &sn, &cs);
    float ev = Q[iq][2*i], ov = Q[iq][2*i+1];
    Q[iq][2*i] = ev * cs - ov * sn; Q[iq][2*i+1] = ev * sn + ov * cs;
  }
  __syncthreads();
  const float scale = 0.17677669529663687f;
  for (int e = t; e < 32 * 96; e += 256) {
    int iq = e / 96, j = e - iq * 96;
    float s = 0.f;
#pragma unroll
    for (int d = 0; d < 32; d++) s = fmaf(Q[iq][d], KV[j][d], s);
    P[iq][j] = s * scale + kbias[j];
  }
  __syncthreads();
#pragma unroll
  for (int i = 0; i < 12; i++) {            // V2 into KV smem
    int e = t + i * 256;
    int r = e >> 5, d = e & 31;
    KV[r][d] = kv2[kvbase + (size_t)r * 512 + 256 + d];
  }
  const int w = t >> 5, lane = t & 31;
#pragma unroll
  for (int rr = 0; rr < 4; rr++) {          // softmax: 32 rows / 8 warps
    int r = w * 4 + rr;
    float x0 = P[r][lane], x1 = P[r][lane + 32], x2 = P[r][lane + 64];
    float mx = fmaxf(x0, fmaxf(x1, x2));
#pragma unroll
    for (int o = 16; o > 0; o >>= 1) mx = fmaxf(mx, __shfl_xor_sync(0xffffffffu, mx, o));
    float e0 = __expf(x0 - mx), e1 = __expf(x1 - mx), e2 = __expf(x2 - mx);
    float sm = e0 + e1 + e2;
#pragma unroll
    for (int o = 16; o > 0; o >>= 1) sm += __shfl_xor_sync(0xffffffffu, sm, o);
    float inv = 1.f / sm;
    P[r][lane] = e0 * inv; P[r][lane + 32] = e1 * inv; P[r][lane + 64] = e2 * inv;
  }
  __syncthreads();
#pragma unroll
  for (int ii = 0; ii < 4; ii++) {
    int e = t + ii * 256;
    int iq = e >> 5, d = e & 31;
    float o = 0.f;
#pragma unroll
    for (int j = 0; j < 96; j++) o = fmaf(P[iq][j], KV[j][d], o);
    out[(tokbase + (size_t)(96 + iq) * 64) * 256 + h * 32 + d] = o;
  }
}

// ---------------- LayerNorm over E=256 (one warp per row) ----------------
__global__ __launch_bounds__(256)
void ln_kernel(const float* __restrict__ x, const float* __restrict__ g,
               const float* __restrict__ bb, float* __restrict__ y)
{
  const int w = threadIdx.x >> 5, lane = threadIdx.x & 31;
  const size_t row = (size_t)blockIdx.x * 8 + w;
  const float* xr = x + row * 256 + lane * 8;
  float4 v0 = *(const float4*)xr;
  float4 v1 = *(const float4*)(xr + 4);
  float s = v0.x+v0.y+v0.z+v0.w + v1.x+v1.y+v1.z+v1.w;
#pragma unroll
  for (int o = 16; o > 0; o >>= 1) s += __shfl_xor_sync(0xffffffffu, s, o);
  float mean = s * 0.00390625f;
  float d0=v0.x-mean, d1=v0.y-mean, d2=v0.z-mean, d3=v0.w-mean;
  float d4=v1.x-mean, d5=v1.y-mean, d6=v1.z-mean, d7=v1.w-mean;
  float q = d0*d0+d1*d1+d2*d2+d3*d3+d4*d4+d5*d5+d6*d6+d7*d7;
#pragma unroll
  for (int o = 16; o > 0; o >>= 1) q += __shfl_xor_sync(0xffffffffu, q, o);
  float rstd = rsqrtf(q * 0.00390625f + 1e-5f);
  const float* gp = g + lane * 8; const float* bp = bb + lane * 8;
  float4 g0 = *(const float4*)gp, g1 = *(const float4*)(gp + 4);
  float4 b0 = *(const float4*)bp, b1 = *(const float4*)(bp + 4);
  float* yr = y + row * 256 + lane * 8;
  *(float4*)yr       = make_float4(d0*rstd*g0.x+b0.x, d1*rstd*g0.y+b0.y,
                                   d2*rstd*g0.z+b0.z, d3*rstd*g0.w+b0.w);
  *(float4*)(yr + 4) = make_float4(d4*rstd*g1.x+b1.x, d5*rstd*g1.y+b1.y,
                                   d6*rstd*g1.z+b1.z, d7*rstd*g1.w+b1.w);
}

// ---------------- nan_to_num ----------------
__global__ void nan2num_kernel(const float* __restrict__ in, float* __restrict__ out)
{
  size_t i = (size_t)blockIdx.x * blockDim.x + threadIdx.x;
  float4 v = ((const float4*)in)[i];
  v.x = isfinite(v.x) ? v.x : 0.f;
  v.y = isfinite(v.y) ? v.y : 0.f;
  v.z = isfinite(v.z) ? v.z : 0.f;
  v.w = isfinite(v.w) ? v.w : 0.f;
  ((float4*)out)[i] = v;
}

// ---------------- launch ----------------
extern "C" void kernel_launch(void* const* d_in, const int* in_sizes, int n_in,
                              void* d_out, int out_size)
{
  const float* src  = (const float*)d_in[0];
  const int*   mask = (const int*)d_in[1];
  // ctx_qry_split_index may be materialized as a size-1 tensor or dropped.
  int base = (in_sizes[2] == 1) ? 3 : 2;
  const float* y_in_w  = (const float*)d_in[base + 0];
  const float* y_in_b  = (const float*)d_in[base + 1];
  const float* y_out_w = (const float*)d_in[base + 2];
  const float* y_out_b = (const float*)d_in[base + 3];
  const float* x_in_w  = (const float*)d_in[base + 4];
  const float* x_in_b  = (const float*)d_in[base + 5];
  const float* x_out_w = (const float*)d_in[base + 6];
  const float* x_out_b = (const float*)d_in[base + 7];
  const float* w1  = (const float*)d_in[base + 8];
  const float* b1  = (const float*)d_in[base + 9];
  const float* w2  = (const float*)d_in[base + 10];
  const float* b2  = (const float*)d_in[base + 11];
  const float* n1g = (const float*)d_in[base + 12];
  const float* n1b = (const float*)d_in[base + 13];
  const float* n2g = (const float*)d_in[base + 14];
  const float* n2b = (const float*)d_in[base + 15];
  const float* n3g = (const float*)d_in[base + 16];
  const float* n3b = (const float*)d_in[base + 17];
  float* out = (float*)d_out;

  float *x0, *qkvb, *attb, *xnb, *yb, *kv2b, *zb, *hb;
  cudaGetSymbolAddress((void**)&x0,   g_x0);
  cudaGetSymbolAddress((void**)&qkvb, g_qkv);
  cudaGetSymbolAddress((void**)&attb, g_att);
  cudaGetSymbolAddress((void**)&xnb,  g_xn);
  cudaGetSymbolAddress((void**)&yb,   g_y);
  cudaGetSymbolAddress((void**)&kv2b, g_kv2);
  cudaGetSymbolAddress((void**)&zb,   g_z);
  cudaGetSymbolAddress((void**)&hb,   g_h);

  // Stage 1: row-axis self-attention + residual + LN1
  nan2num_kernel<<<16384, 256>>>(src, x0);
  gemm_nt<MAP_ID, MAP_ID, EPI_B  ><<<dim3(6, 512), 256>>>(x0, y_in_w, y_in_b, qkvb, nullptr, 65536, 768, 256);
  att1_kernel<<<8192, 256>>>(qkvb, attb);
  gemm_nt<MAP_ID, MAP_ID, EPI_RES><<<dim3(2, 512), 256>>>(attb, y_out_w, y_out_b, yb, x0, 65536, 256, 256);
  ln_kernel<<<8192, 256>>>(yb, n1g, n1b, xnb);

  // Stage 2: column-axis attention with RoPE + key-padding mask
  gemm_nt<MAP_ID, MAP_ID, EPI_B  ><<<dim3(6, 512), 256>>>(xnb, x_in_w, x_in_b, qkvb, nullptr, 65536, 768, 256);
  att2_ctx_kernel<<<8192, 256>>>(qkvb, mask, attb);
  gemm_nt<MAP_CTX, MAP_CTX, EPI_RES><<<dim3(2, 384), 256>>>(attb, x_out_w, x_out_b, yb, xnb, 49152, 256, 256);
  gemm_nt<MAP_CTX, MAP_ID,  EPI_B  ><<<dim3(4, 384), 256>>>(yb, x_in_w + 256 * 256, x_in_b + 256, kv2b, nullptr, 49152, 512, 256);
  att2_qry_kernel<<<4096, 256>>>(qkvb, kv2b, mask, attb);
  gemm_nt<MAP_QRY, MAP_QRY, EPI_RES><<<dim3(2, 128), 256>>>(attb, x_out_w, x_out_b, yb, xnb, 16384, 256, 256);

  // LN2 + MLP + residual + LN3
  ln_kernel<<<8192, 256>>>(yb, n2g, n2b, zb);
  gemm_nt<MAP_ID, MAP_ID, EPI_GELU><<<dim3(8, 512), 256>>>(zb, w1, b1, hb, nullptr, 65536, 1024, 256);
  gemm_nt<MAP_ID, MAP_ID, EPI_RES ><<<dim3(2, 512), 256>>>(hb, w2, b2, x0, zb, 65536, 256, 1024);
  ln_kernel<<<8192, 256>>>(x0, n3g, n3b, out);
}

// round 8
// speedup vs baseline: 1.9222x; 1.9222x over previous
#include <cuda_runtime.h>
#include <cuda_bf16.h>
#include <math.h>

// ---------------- static problem dims ----------------
// src: (8, 128, 64, 256). Token n = (b*128 + r)*64 + c  = b*8192 + r*64 + c
// Stage1: sequences (b1 = b*128+r) of length C=64.
// Stage2: sequences (b2 = b*64 + c) of length R=128, split S=96 ctx / 32 qry.
#define NTOK 65536
#define EDIM 256

// ---------------- scratch (device globals; no allocations) ----------------
__device__ float g_x0 [(size_t)NTOK * 256];
__device__ float g_qkv[(size_t)NTOK * 768];
__device__ float g_att[(size_t)NTOK * 256];
__device__ float g_xn [(size_t)NTOK * 256];
__device__ float g_y  [(size_t)NTOK * 256];
__device__ float g_kv2[(size_t)512 * 96 * 512];
__device__ float g_z  [(size_t)NTOK * 256];
__device__ float g_h  [(size_t)NTOK * 1024];

__constant__ float c_invfreq[16] = {
  1.0f, 0.5623413251903491f, 0.31622776601683794f, 0.17782794100389228f,
  0.1f, 0.05623413251903491f, 0.031622776601683794f, 0.017782794100389228f,
  0.01f, 0.005623413251903491f, 0.0031622776601683794f, 0.0017782794100389229f,
  0.001f, 0.0005623413251903491f, 0.00031622776601683794f, 0.00017782794100389227f
};

enum { MAP_ID = 0, MAP_CTX = 1, MAP_QRY = 2 };
enum { EPI_B = 0, EPI_RES = 1, EPI_GELU = 2 };

template<int MAP>
__device__ __forceinline__ int map_row(int m) {
  if (MAP == MAP_ID) {
    return m;
  } else if (MAP == MAP_CTX) {            // m = b2*96 + r,  r in [0,96)
    int b2 = m / 96, r = m - b2 * 96;
    int b = b2 >> 6, c = b2 & 63;
    return b * 8192 + r * 64 + c;
  } else {                                 // m = b2*32 + i,  r = 96 + i
    int b2 = m >> 5, i = m & 31;
    int b = b2 >> 6, c = b2 & 63;
    return b * 8192 + (96 + i) * 64 + c;
  }
}

__device__ __forceinline__ float tf32r(float x) {
  float y;
  asm("cvt.rna.tf32.f32 %0, %1;" : "=f"(y) : "f"(x));
  return y;
}

__device__ __forceinline__ void mma_tf32(float c[4], const unsigned a[4], const unsigned b[2]) {
  asm volatile(
    "mma.sync.aligned.m16n8k8.row.col.f32.tf32.tf32.f32 "
    "{%0,%1,%2,%3}, {%4,%5,%6,%7}, {%8,%9}, {%0,%1,%2,%3};\n"
    : "+f"(c[0]), "+f"(c[1]), "+f"(c[2]), "+f"(c[3])
    : "r"(a[0]), "r"(a[1]), "r"(a[2]), "r"(a[3]), "r"(b[0]), "r"(b[1]));
}

// ---------------- TF32 NT GEMM: C[M,N] = A[M,K] . W[N,K]^T + bias (+epi) ------
// 128x128 tile, BK=16, 256 threads (2x4 warps, 64x32 warp tile), m16n8k8 tf32.
// Register-staged double-buffered smem; RNA-round-to-tf32 at smem store.
template<int MAPA, int MAPC, int EPI>
__global__ __launch_bounds__(256, 2)
void gemm_tf32(const float* __restrict__ A, const float* __restrict__ W,
               const float* __restrict__ bias, float* __restrict__ C,
               const float* __restrict__ Res, int M, int N, int K)
{
  __shared__ float As[2][128][20];
  __shared__ float Bs[2][128][20];
  const int t  = threadIdx.x;
  const int mt = blockIdx.y * 128;
  const int nt = blockIdx.x * 128;
  const int lm = t >> 2;            // 0..63
  const int lk = (t & 3) << 2;      // 0,4,8,12

  const int arow0 = map_row<MAPA>(mt + lm);
  const int arow1 = map_row<MAPA>(mt + lm + 64);
  const float* Ap0 = A + (size_t)arow0 * K + lk;
  const float* Ap1 = A + (size_t)arow1 * K + lk;
  const float* Wp0 = W + (size_t)(nt + lm) * K + lk;
  const float* Wp1 = W + (size_t)(nt + lm + 64) * K + lk;

  const int w = t >> 5, lane = t & 31;
  const int wm = w & 1, wn = w >> 1;    // 2 (M) x 4 (N)
  const int g = lane >> 2, tq = lane & 3;

  float acc[4][4][4];
#pragma unroll
  for (int i = 0; i < 4; i++)
#pragma unroll
    for (int j = 0; j < 4; j++)
#pragma unroll
      for (int r = 0; r < 4; r++) acc[i][j][r] = 0.f;

  float4 sa0 = *(const float4*)Ap0;
  float4 sa1 = *(const float4*)Ap1;
  float4 sb0 = *(const float4*)Wp0;
  float4 sb1 = *(const float4*)Wp1;

  int buf = 0;
  for (int k0 = 0; k0 < K; k0 += 16) {
    // store staged tile (rounded to tf32) into current buffer
    *(float4*)&As[buf][lm][lk]      = make_float4(tf32r(sa0.x), tf32r(sa0.y), tf32r(sa0.z), tf32r(sa0.w));
    *(float4*)&As[buf][lm + 64][lk] = make_float4(tf32r(sa1.x), tf32r(sa1.y), tf32r(sa1.z), tf32r(sa1.w));
    *(float4*)&Bs[buf][lm][lk]      = make_float4(tf32r(sb0.x), tf32r(sb0.y), tf32r(sb0.z), tf32r(sb0.w));
    *(float4*)&Bs[buf][lm + 64][lk] = make_float4(tf32r(sb1.x), tf32r(sb1.y), tf32r(sb1.z), tf32r(sb1.w));
    __syncthreads();
    if (k0 + 16 < K) {
      sa0 = *(const float4*)(Ap0 + k0 + 16);
      sa1 = *(const float4*)(Ap1 + k0 + 16);
      sb0 = *(const float4*)(Wp0 + k0 + 16);
      sb1 = *(const float4*)(Wp1 + k0 + 16);
    }
#pragma unroll
    for (int ks = 0; ks < 16; ks += 8) {
      unsigned ar[4][4], br[4][2];
#pragma unroll
      for (int im = 0; im < 4; im++) {
        int m = wm * 64 + im * 16;
        ar[im][0] = __float_as_uint(As[buf][m + g    ][ks + tq    ]);
        ar[im][1] = __float_as_uint(As[buf][m + g + 8][ks + tq    ]);
        ar[im][2] = __float_as_uint(As[buf][m + g    ][ks + tq + 4]);
        ar[im][3] = __float_as_uint(As[buf][m + g + 8][ks + tq + 4]);
      }
#pragma unroll
      for (int jn = 0; jn < 4; jn++) {
        int n = wn * 32 + jn * 8;
        br[jn][0] = __float_as_uint(Bs[buf][n + g][ks + tq    ]);
        br[jn][1] = __float_as_uint(Bs[buf][n + g][ks + tq + 4]);
      }
#pragma unroll
      for (int im = 0; im < 4; im++)
#pragma unroll
        for (int jn = 0; jn < 4; jn++)
          mma_tf32(acc[im][jn], ar[im], br[jn]);
    }
    buf ^= 1;
  }

  // epilogue: bias (+residual | +gelu); each lane owns 2 rows x 2 cols per tile
#pragma unroll
  for (int im = 0; im < 4; im++) {
    int r0 = mt + wm * 64 + im * 16 + g;
    int cr0 = map_row<MAPC>(r0);
    int cr1 = map_row<MAPC>(r0 + 8);
#pragma unroll
    for (int jn = 0; jn < 4; jn++) {
      int n = nt + wn * 32 + jn * 8 + 2 * tq;
      float2 bv = *(const float2*)&bias[n];
      float o0 = acc[im][jn][0] + bv.x, o1 = acc[im][jn][1] + bv.y;
      float o2 = acc[im][jn][2] + bv.x, o3 = acc[im][jn][3] + bv.y;
      if (EPI == EPI_RES) {
        float2 v0 = *(const float2*)&Res[(size_t)cr0 * N + n];
        float2 v1 = *(const float2*)&Res[(size_t)cr1 * N + n];
        o0 += v0.x; o1 += v0.y; o2 += v1.x; o3 += v1.y;
      }
      if (EPI == EPI_GELU) {
        o0 = 0.5f * o0 * (1.0f + erff(o0 * 0.7071067811865475f));
        o1 = 0.5f * o1 * (1.0f + erff(o1 * 0.7071067811865475f));
        o2 = 0.5f * o2 * (1.0f + erff(o2 * 0.7071067811865475f));
        o3 = 0.5f * o3 * (1.0f + erff(o3 * 0.7071067811865475f));
      }
      *(float2*)&C[(size_t)cr0 * N + n] = make_float2(o0, o1);
      *(float2*)&C[(size_t)cr1 * N + n] = make_float2(o2, o3);
    }
  }
}

// ---------------- stage-1 attention: per (b1, h), L=64, hd=32 ----------------
__global__ __launch_bounds__(256)
void att1_kernel(const float* __restrict__ qkv, float* __restrict__ out)
{
  __shared__ float Q[64][33], K[64][33], V[64][33], P[64][65];
  const int blk = blockIdx.x;
  const int b1 = blk >> 3, h = blk & 7;
  const int t = threadIdx.x;
  const size_t base = (size_t)b1 * 64 * 768 + h * 32;
#pragma unroll
  for (int i = 0; i < 8; i++) {
    int e = t + i * 256;
    int c = e >> 5, d = e & 31;
    size_t o = base + (size_t)c * 768 + d;
    Q[c][d] = qkv[o];
    K[c][d] = qkv[o + 256];
    V[c][d] = qkv[o + 512];
  }
  __syncthreads();
  const float scale = 0.17677669529663687f;   // 1/sqrt(32)
#pragma unroll
  for (int i = 0; i < 16; i++) {
    int e = t + i * 256;
    int iq = e >> 6, j = e & 63;
    float s = 0.f;
#pragma unroll
    for (int d = 0; d < 32; d++) s = fmaf(Q[iq][d], K[j][d], s);
    P[iq][j] = s * scale;
  }
  __syncthreads();
  const int w = t >> 5, lane = t & 31;
#pragma unroll
  for (int rr = 0; rr < 8; rr++) {
    int r = w * 8 + rr;
    float a = P[r][lane], b = P[r][lane + 32];
    float mx = fmaxf(a, b);
#pragma unroll
    for (int o = 16; o > 0; o >>= 1) mx = fmaxf(mx, __shfl_xor_sync(0xffffffffu, mx, o));
    float ea = __expf(a - mx), eb = __expf(b - mx);
    float sm = ea + eb;
#pragma unroll
    for (int o = 16; o > 0; o >>= 1) sm += __shfl_xor_sync(0xffffffffu, sm, o);
    float inv = 1.f / sm;
    P[r][lane] = ea * inv; P[r][lane + 32] = eb * inv;
  }
  __syncthreads();
#pragma unroll
  for (int i = 0; i < 8; i++) {
    int e = t + i * 256;
    int c = e >> 5, d = e & 31;
    float o = 0.f;
#pragma unroll
    for (int j = 0; j < 64; j++) o = fmaf(P[c][j], V[j][d], o);
    out[(size_t)(b1 * 64 + c) * 256 + h * 32 + d] = o;
  }
}

// ---------------- stage-2 ctx attention: per (b2, h, half), 48 q-rows, 96 keys ----
__global__ __launch_bounds__(256)
void att2_ctx_kernel(const float* __restrict__ qkv, const int* __restrict__ mask,
                     float* __restrict__ out)
{
  __shared__ float Q[48][33], KV[96][33], P[48][97];
  __shared__ float kbias[96];
  const int blk = blockIdx.x;
  const int half = blk & 1, h = (blk >> 1) & 7, b2 = blk >> 4;
  const int b = b2 >> 6, c = b2 & 63;
  const int t = threadIdx.x;
  const int q0 = half * 48;
  const size_t tokbase = (size_t)b * 8192 + c;

#pragma unroll
  for (int i = 0; i < 12; i++) {            // K: 96x32
    int e = t + i * 256;
    int r = e >> 5, d = e & 31;
    KV[r][d] = qkv[(tokbase + (size_t)r * 64) * 768 + 256 + h * 32 + d];
  }
#pragma unroll
  for (int i = 0; i < 6; i++) {             // Q: 48x32
    int e = t + i * 256;
    int iq = e >> 5, d = e & 31;
    Q[iq][d] = qkv[(tokbase + (size_t)(q0 + iq) * 64) * 768 + h * 32 + d];
  }
  if (t < 96) kbias[t] = (mask[b * 128 + t] > 0) ? 0.f : -1e9f;
  __syncthreads();
  for (int e = t; e < 96 * 16; e += 256) {  // RoPE K (pos r)
    int r = e >> 4, i = e & 15;
    float sn, cs; sincosf((float)r * c_invfreq[i], &sn, &cs);
    float ev = KV[r][2*i], ov = KV[r][2*i+1];
    KV[r][2*i] = ev * cs - ov * sn; KV[r][2*i+1] = ev * sn + ov * cs;
  }
  for (int e = t; e < 48 * 16; e += 256) {  // RoPE Q (pos q0+iq)
    int iq = e >> 4, i = e & 15;
    float sn, cs; sincosf((float)(q0 + iq) * c_invfreq[i], &sn, &cs);
    float ev = Q[iq][2*i], ov = Q[iq][2*i+1];
    Q[iq][2*i] = ev * cs - ov * sn; Q[iq][2*i+1] = ev * sn + ov * cs;
  }
  __syncthreads();
  const float scale = 0.17677669529663687f;
  for (int e = t; e < 48 * 96; e += 256) {
    int iq = e / 96, j = e - iq * 96;
    float s = 0.f;
#pragma unroll
    for (int d = 0; d < 32; d++) s = fmaf(Q[iq][d], KV[j][d], s);
    P[iq][j] = s * scale + kbias[j];
  }
  __syncthreads();
#pragma unroll
  for (int i = 0; i < 12; i++) {            // reuse KV smem for V
    int e = t + i * 256;
    int r = e >> 5, d = e & 31;
    KV[r][d] = qkv[(tokbase + (size_t)r * 64) * 768 + 512 + h * 32 + d];
  }
  const int w = t >> 5, lane = t & 31;
#pragma unroll
  for (int rr = 0; rr < 6; rr++) {          // softmax: 48 rows / 8 warps
    int r = w * 6 + rr;
    float x0 = P[r][lane], x1 = P[r][lane + 32], x2 = P[r][lane + 64];
    float mx = fmaxf(x0, fmaxf(x1, x2));
#pragma unroll
    for (int o = 16; o > 0; o >>= 1) mx = fmaxf(mx, __shfl_xor_sync(0xffffffffu, mx, o));
    float e0 = __expf(x0 - mx), e1 = __expf(x1 - mx), e2 = __expf(x2 - mx);
    float sm = e0 + e1 + e2;
#pragma unroll
    for (int o = 16; o > 0; o >>= 1) sm += __shfl_xor_sync(0xffffffffu, sm, o);
    float inv = 1.f / sm;
    P[r][lane] = e0 * inv; P[r][lane + 32] = e1 * inv; P[r][lane + 64] = e2 * inv;
  }
  __syncthreads();
#pragma unroll
  for (int ii = 0; ii < 6; ii++) {
    int e = t + ii * 256;
    int iq = e >> 5, d = e & 31;
    float o = 0.f;
#pragma unroll
    for (int j = 0; j < 96; j++) o = fmaf(P[iq][j], KV[j][d], o);
    out[(tokbase + (size_t)(q0 + iq) * 64) * 256 + h * 32 + d] = o;
  }
}

// ---------------- stage-2 qry attention: per (b2, h), 32 q-rows, 96 keys ----------
__global__ __launch_bounds__(256)
void att2_qry_kernel(const float* __restrict__ qkv, const float* __restrict__ kv2,
                     const int* __restrict__ mask, float* __restrict__ out)
{
  __shared__ float Q[32][33], KV[96][33], P[32][97];
  __shared__ float kbias[96];
  const int blk = blockIdx.x;
  const int h = blk & 7, b2 = blk >> 3;
  const int b = b2 >> 6, c = b2 & 63;
  const int t = threadIdx.x;
  const size_t tokbase = (size_t)b * 8192 + c;
  const size_t kvbase = (size_t)b2 * 96 * 512 + h * 32;

#pragma unroll
  for (int i = 0; i < 12; i++) {            // K2 (updated ctx)
    int e = t + i * 256;
    int r = e >> 5, d = e & 31;
    KV[r][d] = kv2[kvbase + (size_t)r * 512 + d];
  }
#pragma unroll
  for (int i = 0; i < 4; i++) {             // Q (qry tokens)
    int e = t + i * 256;
    int iq = e >> 5, d = e & 31;
    Q[iq][d] = qkv[(tokbase + (size_t)(96 + iq) * 64) * 768 + h * 32 + d];
  }
  if (t < 96) kbias[t] = (mask[b * 128 + t] > 0) ? 0.f : -1e9f;
  __syncthreads();
  for (int e = t; e < 96 * 16; e += 256) {  // RoPE K (pos r)
    int r = e >> 4, i = e & 15;
    float sn, cs; sincosf((float)r * c_invfreq[i], &sn, &cs);
    float ev = KV[r][2*i], ov = KV[r][2*i+1];
    KV[r][2*i] = ev * cs - ov * sn; KV[r][2*i+1] = ev * sn + ov * cs;
  }
  for (int e = t; e < 32 * 16; e += 256) {  // RoPE Q (pos 96+iq)
    int iq = e >> 4, i = e & 15;
    float sn, cs; sincosf((float)(96 + iq) * c_invfreq[i], &sn, &cs);
    float ev = Q[iq][2*i], ov = Q[iq][2*i+1];
    Q[iq][2*i] = ev * cs - ov * sn; Q[iq][2*i+1] = ev * sn + ov * cs;
  }
  __syncthreads();
  const float scale = 0.17677669529663687f;
  for (int e = t; e < 32 * 96; e += 256) {
    int iq = e / 96, j = e - iq * 96;
    float s = 0.f;
#pragma unroll
    for (int d = 0; d < 32; d++) s = fmaf(Q[iq][d], KV[j][d], s);
    P[iq][j] = s * scale + kbias[j];
  }
  __syncthreads();
#pragma unroll
  for (int i = 0; i < 12; i++) {            // V2 into KV smem
    int e = t + i * 256;
    int r = e >> 5, d = e & 31;
    KV[r][d] = kv2[kvbase + (size_t)r * 512 + 256 + d];
  }
  const int w = t >> 5, lane = t & 31;
#pragma unroll
  for (int rr = 0; rr < 4; rr++) {          // softmax: 32 rows / 8 warps
    int r = w * 4 + rr;
    float x0 = P[r][lane], x1 = P[r][lane + 32], x2 = P[r][lane + 64];
    float mx = fmaxf(x0, fmaxf(x1, x2));
#pragma unroll
    for (int o = 16; o > 0; o >>= 1) mx = fmaxf(mx, __shfl_xor_sync(0xffffffffu, mx, o));
    float e0 = __expf(x0 - mx), e1 = __expf(x1 - mx), e2 = __expf(x2 - mx);
    float sm = e0 + e1 + e2;
#pragma unroll
    for (int o = 16; o > 0; o >>= 1) sm += __shfl_xor_sync(0xffffffffu, sm, o);
    float inv = 1.f / sm;
    P[r][lane] = e0 * inv; P[r][lane + 32] = e1 * inv; P[r][lane + 64] = e2 * inv;
  }
  __syncthreads();
#pragma unroll
  for (int ii = 0; ii < 4; ii++) {
    int e = t + ii * 256;
    int iq = e >> 5, d = e & 31;
    float o = 0.f;
#pragma unroll
    for (int j = 0; j < 96; j++) o = fmaf(P[iq][j], KV[j][d], o);
    out[(tokbase + (size_t)(96 + iq) * 64) * 256 + h * 32 + d] = o;
  }
}

// ---------------- LayerNorm over E=256 (one warp per row) ----------------
__global__ __launch_bounds__(256)
void ln_kernel(const float* __restrict__ x, const float* __restrict__ g,
               const float* __restrict__ bb, float* __restrict__ y)
{
  const int w = threadIdx.x >> 5, lane = threadIdx.x & 31;
  const size_t row = (size_t)blockIdx.x * 8 + w;
  const float* xr = x + row * 256 + lane * 8;
  float4 v0 = *(const float4*)xr;
  float4 v1 = *(const float4*)(xr + 4);
  float s = v0.x+v0.y+v0.z+v0.w + v1.x+v1.y+v1.z+v1.w;
#pragma unroll
  for (int o = 16; o > 0; o >>= 1) s += __shfl_xor_sync(0xffffffffu, s, o);
  float mean = s * 0.00390625f;
  float d0=v0.x-mean, d1=v0.y-mean, d2=v0.z-mean, d3=v0.w-mean;
  float d4=v1.x-mean, d5=v1.y-mean, d6=v1.z-mean, d7=v1.w-mean;
  float q = d0*d0+d1*d1+d2*d2+d3*d3+d4*d4+d5*d5+d6*d6+d7*d7;
#pragma unroll
  for (int o = 16; o > 0; o >>= 1) q += __shfl_xor_sync(0xffffffffu, q, o);
  float rstd = rsqrtf(q * 0.00390625f + 1e-5f);
  const float* gp = g + lane * 8; const float* bp = bb + lane * 8;
  float4 g0 = *(const float4*)gp, g1 = *(const float4*)(gp + 4);
  float4 b0 = *(const float4*)bp, b1 = *(const float4*)(bp + 4);
  float* yr = y + row * 256 + lane * 8;
  *(float4*)yr       = make_float4(d0*rstd*g0.x+b0.x, d1*rstd*g0.y+b0.y,
                                   d2*rstd*g0.z+b0.z, d3*rstd*g0.w+b0.w);
  *(float4*)(yr + 4) = make_float4(d4*rstd*g1.x+b1.x, d5*rstd*g1.y+b1.y,
                                   d6*rstd*g1.z+b1.z, d7*rstd*g1.w+b1.w);
}

// ---------------- nan_to_num ----------------
__global__ void nan2num_kernel(const float* __restrict__ in, float* __restrict__ out)
{
  size_t i = (size_t)blockIdx.x * blockDim.x + threadIdx.x;
  float4 v = ((const float4*)in)[i];
  v.x = isfinite(v.x) ? v.x : 0.f;
  v.y = isfinite(v.y) ? v.y : 0.f;
  v.z = isfinite(v.z) ? v.z : 0.f;
  v.w = isfinite(v.w) ? v.w : 0.f;
  ((float4*)out)[i] = v;
}

// ---------------- launch ----------------
extern "C" void kernel_launch(void* const* d_in, const int* in_sizes, int n_in,
                              void* d_out, int out_size)
{
  const float* src  = (const float*)d_in[0];
  const int*   mask = (const int*)d_in[1];
  int base = (in_sizes[2] == 1) ? 3 : 2;
  const float* y_in_w  = (const float*)d_in[base + 0];
  const float* y_in_b  = (const float*)d_in[base + 1];
  const float* y_out_w = (const float*)d_in[base + 2];
  const float* y_out_b = (const float*)d_in[base + 3];
  const float* x_in_w  = (const float*)d_in[base + 4];
  const float* x_in_b  = (const float*)d_in[base + 5];
  const float* x_out_w = (const float*)d_in[base + 6];
  const float* x_out_b = (const float*)d_in[base + 7];
  const float* w1  = (const float*)d_in[base + 8];
  const float* b1  = (const float*)d_in[base + 9];
  const float* w2  = (const float*)d_in[base + 10];
  const float* b2  = (const float*)d_in[base + 11];
  const float* n1g = (const float*)d_in[base + 12];
  const float* n1b = (const float*)d_in[base + 13];
  const float* n2g = (const float*)d_in[base + 14];
  const float* n2b = (const float*)d_in[base + 15];
  const float* n3g = (const float*)d_in[base + 16];
  const float* n3b = (const float*)d_in[base + 17];
  float* out = (float*)d_out;

  float *x0, *qkvb, *attb, *xnb, *yb, *kv2b, *zb, *hb;
  cudaGetSymbolAddress((void**)&x0,   g_x0);
  cudaGetSymbolAddress((void**)&qkvb, g_qkv);
  cudaGetSymbolAddress((void**)&attb, g_att);
  cudaGetSymbolAddress((void**)&xnb,  g_xn);
  cudaGetSymbolAddress((void**)&yb,   g_y);
  cudaGetSymbolAddress((void**)&kv2b, g_kv2);
  cudaGetSymbolAddress((void**)&zb,   g_z);
  cudaGetSymbolAddress((void**)&hb,   g_h);

  // Stage 1: row-axis self-attention + residual + LN1
  nan2num_kernel<<<16384, 256>>>(src, x0);
  gemm_tf32<MAP_ID, MAP_ID, EPI_B  ><<<dim3(6, 512), 256>>>(x0, y_in_w, y_in_b, qkvb, nullptr, 65536, 768, 256);
  att1_kernel<<<8192, 256>>>(qkvb, attb);
  gemm_tf32<MAP_ID, MAP_ID, EPI_RES><<<dim3(2, 512), 256>>>(attb, y_out_w, y_out_b, yb, x0, 65536, 256, 256);
  ln_kernel<<<8192, 256>>>(yb, n1g, n1b, xnb);

  // Stage 2: column-axis attention with RoPE + key-padding mask
  gemm_tf32<MAP_ID, MAP_ID, EPI_B  ><<<dim3(6, 512), 256>>>(xnb, x_in_w, x_in_b, qkvb, nullptr, 65536, 768, 256);
  att2_ctx_kernel<<<8192, 256>>>(qkvb, mask, attb);
  gemm_tf32<MAP_CTX, MAP_CTX, EPI_RES><<<dim3(2, 384), 256>>>(attb, x_out_w, x_out_b, yb, xnb, 49152, 256, 256);
  gemm_tf32<MAP_CTX, MAP_ID,  EPI_B  ><<<dim3(4, 384), 256>>>(yb, x_in_w + 256 * 256, x_in_b + 256, kv2b, nullptr, 49152, 512, 256);
  att2_qry_kernel<<<4096, 256>>>(qkvb, kv2b, mask, attb);
  gemm_tf32<MAP_QRY, MAP_QRY, EPI_RES><<<dim3(2, 128), 256>>>(attb, x_out_w, x_out_b, yb, xnb, 16384, 256, 256);

  // LN2 + MLP + residual + LN3
  ln_kernel<<<8192, 256>>>(yb, n2g, n2b, zb);
  gemm_tf32<MAP_ID, MAP_ID, EPI_GELU><<<dim3(8, 512), 256>>>(zb, w1, b1, hb, nullptr, 65536, 1024, 256);
  gemm_tf32<MAP_ID, MAP_ID, EPI_RES ><<<dim3(2, 512), 256>>>(hb, w2, b2, x0, zb, 65536, 256, 1024);
  ln_kernel<<<8192, 256>>>(x0, n3g, n3b, out);
}

// round 11
// speedup vs baseline: 2.6771x; 1.3927x over previous
#include <cuda_runtime.h>
#include <cuda_bf16.h>
#include <math.h>

// ---------------- static problem dims ----------------
// src: (8, 128, 64, 256). Token n = (b*128 + r)*64 + c  = b*8192 + r*64 + c
// Stage1: sequences (b1 = b*128+r) of length C=64.
// Stage2: sequences (b2 = b*64 + c) of length R=128, split S=96 ctx / 32 qry.
#define NTOK 65536
#define EDIM 256

// ---------------- scratch (device globals; no allocations) ----------------
__device__ float g_x0 [(size_t)NTOK * 256];
__device__ float g_qkv[(size_t)NTOK * 768];
__device__ float g_att[(size_t)NTOK * 256];
__device__ float g_xn [(size_t)NTOK * 256];
__device__ float g_y  [(size_t)NTOK * 256];
__device__ float g_kv2[(size_t)512 * 96 * 512];
__device__ float g_z  [(size_t)NTOK * 256];
__device__ float g_h  [(size_t)NTOK * 1024];

__constant__ float c_invfreq[16] = {
  1.0f, 0.5623413251903491f, 0.31622776601683794f, 0.17782794100389228f,
  0.1f, 0.05623413251903491f, 0.031622776601683794f, 0.017782794100389228f,
  0.01f, 0.005623413251903491f, 0.0031622776601683794f, 0.0017782794100389229f,
  0.001f, 0.0005623413251903491f, 0.00031622776601683794f, 0.00017782794100389227f
};

enum { MAP_ID = 0, MAP_CTX = 1, MAP_QRY = 2 };
enum { EPI_B = 0, EPI_RES = 1, EPI_GELU = 2 };

template<int MAP>
__device__ __forceinline__ int map_row(int m) {
  if (MAP == MAP_ID) {
    return m;
  } else if (MAP == MAP_CTX) {            // m = b2*96 + r,  r in [0,96)
    int b2 = m / 96, r = m - b2 * 96;
    int b = b2 >> 6, c = b2 & 63;
    return b * 8192 + r * 64 + c;
  } else {                                 // m = b2*32 + i,  r = 96 + i
    int b2 = m >> 5, i = m & 31;
    int b = b2 >> 6, c = b2 & 63;
    return b * 8192 + (96 + i) * 64 + c;
  }
}

__device__ __forceinline__ float tf32r(float x) {
  float y;
  asm("cvt.rna.tf32.f32 %0, %1;" : "=f"(y) : "f"(x));
  return y;
}

__device__ __forceinline__ void mma_tf32(float c[4], const unsigned a[4], const unsigned b[2]) {
  asm volatile(
    "mma.sync.aligned.m16n8k8.row.col.f32.tf32.tf32.f32 "
    "{%0,%1,%2,%3}, {%4,%5,%6,%7}, {%8,%9}, {%0,%1,%2,%3};\n"
    : "+f"(c[0]), "+f"(c[1]), "+f"(c[2]), "+f"(c[3])
    : "r"(a[0]), "r"(a[1]), "r"(a[2]), "r"(a[3]), "r"(b[0]), "r"(b[1]));
}

// ---------------- TF32 NT GEMM: C[M,N] = A[M,K] . W[N,K]^T + bias (+epi) ------
template<int MAPA, int MAPC, int EPI>
__global__ __launch_bounds__(256, 2)
void gemm_tf32(const float* __restrict__ A, const float* __restrict__ W,
               const float* __restrict__ bias, float* __restrict__ C,
               const float* __restrict__ Res, int M, int N, int K)
{
  __shared__ float As[2][128][20];
  __shared__ float Bs[2][128][20];
  const int t  = threadIdx.x;
  const int mt = blockIdx.y * 128;
  const int nt = blockIdx.x * 128;
  const int lm = t >> 2;
  const int lk = (t & 3) << 2;

  const int arow0 = map_row<MAPA>(mt + lm);
  const int arow1 = map_row<MAPA>(mt + lm + 64);
  const float* Ap0 = A + (size_t)arow0 * K + lk;
  const float* Ap1 = A + (size_t)arow1 * K + lk;
  const float* Wp0 = W + (size_t)(nt + lm) * K + lk;
  const float* Wp1 = W + (size_t)(nt + lm + 64) * K + lk;

  const int w = t >> 5, lane = t & 31;
  const int wm = w & 1, wn = w >> 1;
  const int g = lane >> 2, tq = lane & 3;

  float acc[4][4][4];
#pragma unroll
  for (int i = 0; i < 4; i++)
#pragma unroll
    for (int j = 0; j < 4; j++)
#pragma unroll
      for (int r = 0; r < 4; r++) acc[i][j][r] = 0.f;

  float4 sa0 = *(const float4*)Ap0;
  float4 sa1 = *(const float4*)Ap1;
  float4 sb0 = *(const float4*)Wp0;
  float4 sb1 = *(const float4*)Wp1;

  int buf = 0;
  for (int k0 = 0; k0 < K; k0 += 16) {
    *(float4*)&As[buf][lm][lk]      = make_float4(tf32r(sa0.x), tf32r(sa0.y), tf32r(sa0.z), tf32r(sa0.w));
    *(float4*)&As[buf][lm + 64][lk] = make_float4(tf32r(sa1.x), tf32r(sa1.y), tf32r(sa1.z), tf32r(sa1.w));
    *(float4*)&Bs[buf][lm][lk]      = make_float4(tf32r(sb0.x), tf32r(sb0.y), tf32r(sb0.z), tf32r(sb0.w));
    *(float4*)&Bs[buf][lm + 64][lk] = make_float4(tf32r(sb1.x), tf32r(sb1.y), tf32r(sb1.z), tf32r(sb1.w));
    __syncthreads();
    if (k0 + 16 < K) {
      sa0 = *(const float4*)(Ap0 + k0 + 16);
      sa1 = *(const float4*)(Ap1 + k0 + 16);
      sb0 = *(const float4*)(Wp0 + k0 + 16);
      sb1 = *(const float4*)(Wp1 + k0 + 16);
    }
#pragma unroll
    for (int ks = 0; ks < 16; ks += 8) {
      unsigned ar[4][4], br[4][2];
#pragma unroll
      for (int im = 0; im < 4; im++) {
        int m = wm * 64 + im * 16;
        ar[im][0] = __float_as_uint(As[buf][m + g    ][ks + tq    ]);
        ar[im][1] = __float_as_uint(As[buf][m + g + 8][ks + tq    ]);
        ar[im][2] = __float_as_uint(As[buf][m + g    ][ks + tq + 4]);
        ar[im][3] = __float_as_uint(As[buf][m + g + 8][ks + tq + 4]);
      }
#pragma unroll
      for (int jn = 0; jn < 4; jn++) {
        int n = wn * 32 + jn * 8;
        br[jn][0] = __float_as_uint(Bs[buf][n + g][ks + tq    ]);
        br[jn][1] = __float_as_uint(Bs[buf][n + g][ks + tq + 4]);
      }
#pragma unroll
      for (int im = 0; im < 4; im++)
#pragma unroll
        for (int jn = 0; jn < 4; jn++)
          mma_tf32(acc[im][jn], ar[im], br[jn]);
    }
    buf ^= 1;
  }

#pragma unroll
  for (int im = 0; im < 4; im++) {
    int r0 = mt + wm * 64 + im * 16 + g;
    int cr0 = map_row<MAPC>(r0);
    int cr1 = map_row<MAPC>(r0 + 8);
#pragma unroll
    for (int jn = 0; jn < 4; jn++) {
      int n = nt + wn * 32 + jn * 8 + 2 * tq;
      float2 bv = *(const float2*)&bias[n];
      float o0 = acc[im][jn][0] + bv.x, o1 = acc[im][jn][1] + bv.y;
      float o2 = acc[im][jn][2] + bv.x, o3 = acc[im][jn][3] + bv.y;
      if (EPI == EPI_RES) {
        float2 v0 = *(const float2*)&Res[(size_t)cr0 * N + n];
        float2 v1 = *(const float2*)&Res[(size_t)cr1 * N + n];
        o0 += v0.x; o1 += v0.y; o2 += v1.x; o3 += v1.y;
      }
      if (EPI == EPI_GELU) {
        o0 = 0.5f * o0 * (1.0f + erff(o0 * 0.7071067811865475f));
        o1 = 0.5f * o1 * (1.0f + erff(o1 * 0.7071067811865475f));
        o2 = 0.5f * o2 * (1.0f + erff(o2 * 0.7071067811865475f));
        o3 = 0.5f * o3 * (1.0f + erff(o3 * 0.7071067811865475f));
      }
      *(float2*)&C[(size_t)cr0 * N + n] = make_float2(o0, o1);
      *(float2*)&C[(size_t)cr1 * N + n] = make_float2(o2, o3);
    }
  }
}

// ---------------- stage-1 attention (mma): per (b1, h), L=64, hd=32 ----------
__global__ __launch_bounds__(256)
void att1_kernel(const float* __restrict__ qkv, float* __restrict__ out)
{
  __shared__ float Q[64][36], K[64][36], Vt[32][68], P[64][68];
  const int blk = blockIdx.x;
  const int b1 = blk >> 3, h = blk & 7;
  const int t = threadIdx.x;
  const size_t base = (size_t)b1 * 64 * 768 + h * 32;
  const int w = t >> 5, lane = t & 31;
  const int g = lane >> 2, tq = lane & 3;

#pragma unroll
  for (int i = 0; i < 2; i++) {
    int e = t + i * 256;              // 0..511 float4 slots (64x32 / 4)
    int c = e >> 3, d4 = (e & 7) * 4;
    size_t o = base + (size_t)c * 768 + d4;
    float4 q4 = *(const float4*)(qkv + o);
    float4 k4 = *(const float4*)(qkv + o + 256);
    float4 v4 = *(const float4*)(qkv + o + 512);
    *(float4*)&Q[c][d4] = make_float4(tf32r(q4.x), tf32r(q4.y), tf32r(q4.z), tf32r(q4.w));
    *(float4*)&K[c][d4] = make_float4(tf32r(k4.x), tf32r(k4.y), tf32r(k4.z), tf32r(k4.w));
    Vt[d4 + 0][c] = tf32r(v4.x); Vt[d4 + 1][c] = tf32r(v4.y);
    Vt[d4 + 2][c] = tf32r(v4.z); Vt[d4 + 3][c] = tf32r(v4.w);
  }
  __syncthreads();

  const float scale = 0.17677669529663687f;   // 1/sqrt(32)
  {
    const int wm = w >> 1, wn = w & 1;
    const int m0 = wm * 16;
    float c_[4][4];
#pragma unroll
    for (int jn = 0; jn < 4; jn++)
#pragma unroll
      for (int r = 0; r < 4; r++) c_[jn][r] = 0.f;
#pragma unroll
    for (int ks = 0; ks < 32; ks += 8) {
      unsigned ar[4];
      ar[0] = __float_as_uint(Q[m0 + g    ][ks + tq    ]);
      ar[1] = __float_as_uint(Q[m0 + g + 8][ks + tq    ]);
      ar[2] = __float_as_uint(Q[m0 + g    ][ks + tq + 4]);
      ar[3] = __float_as_uint(Q[m0 + g + 8][ks + tq + 4]);
#pragma unroll
      for (int jn = 0; jn < 4; jn++) {
        int n0 = wn * 32 + jn * 8;
        unsigned br[2];
        br[0] = __float_as_uint(K[n0 + g][ks + tq    ]);
        br[1] = __float_as_uint(K[n0 + g][ks + tq + 4]);
        mma_tf32(c_[jn], ar, br);
      }
    }
#pragma unroll
    for (int jn = 0; jn < 4; jn++) {
      int col = wn * 32 + jn * 8 + 2 * tq;
      *(float2*)&P[m0 + g    ][col] = make_float2(c_[jn][0] * scale, c_[jn][1] * scale);
      *(float2*)&P[m0 + g + 8][col] = make_float2(c_[jn][2] * scale, c_[jn][3] * scale);
    }
  }
  __syncthreads();

#pragma unroll
  for (int rr = 0; rr < 8; rr++) {
    int r = w * 8 + rr;
    float a = P[r][lane], b = P[r][lane + 32];
    float mx = fmaxf(a, b);
#pragma unroll
    for (int o = 16; o > 0; o >>= 1) mx = fmaxf(mx, __shfl_xor_sync(0xffffffffu, mx, o));
    float ea = __expf(a - mx), eb = __expf(b - mx);
    float sm = ea + eb;
#pragma unroll
    for (int o = 16; o > 0; o >>= 1) sm += __shfl_xor_sync(0xffffffffu, sm, o);
    float inv = 1.f / sm;
    P[r][lane] = tf32r(ea * inv); P[r][lane + 32] = tf32r(eb * inv);
  }
  __syncthreads();

  {
    const int wm = w >> 1, wn = w & 1;
    const int m0 = wm * 16;
    float o_[2][4];
#pragma unroll
    for (int jn = 0; jn < 2; jn++)
#pragma unroll
      for (int r = 0; r < 4; r++) o_[jn][r] = 0.f;
#pragma unroll
    for (int ks = 0; ks < 64; ks += 8) {
      unsigned ar[4];
      ar[0] = __float_as_uint(P[m0 + g    ][ks + tq    ]);
      ar[1] = __float_as_uint(P[m0 + g + 8][ks + tq    ]);
      ar[2] = __float_as_uint(P[m0 + g    ][ks + tq + 4]);
      ar[3] = __float_as_uint(P[m0 + g + 8][ks + tq + 4]);
#pragma unroll
      for (int jn = 0; jn < 2; jn++) {
        int n0 = wn * 16 + jn * 8;
        unsigned br[2];
        br[0] = __float_as_uint(Vt[n0 + g][ks + tq    ]);
        br[1] = __float_as_uint(Vt[n0 + g][ks + tq + 4]);
        mma_tf32(o_[jn], ar, br);
      }
    }
    int row0 = b1 * 64 + m0 + g;
#pragma unroll
    for (int jn = 0; jn < 2; jn++) {
      int col = h * 32 + wn * 16 + jn * 8 + 2 * tq;
      *(float2*)&out[(size_t)row0 * 256 + col]       = make_float2(o_[jn][0], o_[jn][1]);
      *(float2*)&out[(size_t)(row0 + 8) * 256 + col] = make_float2(o_[jn][2], o_[jn][3]);
    }
  }
}

// ---------------- stage-2 ctx attention (mma): per (b2,h,half): 48 q, 96 keys ----
__global__ __launch_bounds__(256)
void att2_ctx_kernel(const float* __restrict__ qkv, const int* __restrict__ mask,
                     float* __restrict__ out)
{
  __shared__ float Q[48][36], K[96][36], P[48][100];
  __shared__ float kbias[96];
  float* VT = &K[0][0];                 // Vt[d][j] = VT[d*100 + j]; 3200 <= 3456
  const int blk = blockIdx.x;
  const int half = blk & 1, h = (blk >> 1) & 7, b2 = blk >> 4;
  const int b = b2 >> 6, c = b2 & 63;
  const int t = threadIdx.x;
  const int q0 = half * 48;
  const size_t tokbase = (size_t)b * 8192 + c;
  const int w = t >> 5, lane = t & 31;
  const int g = lane >> 2, tq = lane & 3;

  for (int e = t; e < 384; e += 256) {        // Q: 48x32 (raw; rounded post-RoPE)
    int iq = e >> 3, d4 = (e & 7) * 4;
    *(float4*)&Q[iq][d4] = *(const float4*)(qkv + (tokbase + (size_t)(q0 + iq) * 64) * 768 + h * 32 + d4);
  }
#pragma unroll
  for (int i = 0; i < 3; i++) {               // K: 96x32
    int e = t + i * 256;
    int r = e >> 3, d4 = (e & 7) * 4;
    *(float4*)&K[r][d4] = *(const float4*)(qkv + (tokbase + (size_t)r * 64) * 768 + 256 + h * 32 + d4);
  }
  if (t < 96) kbias[t] = (mask[b * 128 + t] > 0) ? 0.f : -1e9f;
  __syncthreads();
  for (int e = t; e < 96 * 16; e += 256) {    // RoPE K (pos r) + round
    int r = e >> 4, i = e & 15;
    float sn, cs; sincosf((float)r * c_invfreq[i], &sn, &cs);
    float ev = K[r][2*i], ov = K[r][2*i+1];
    K[r][2*i] = tf32r(ev * cs - ov * sn); K[r][2*i+1] = tf32r(ev * sn + ov * cs);
  }
  for (int e = t; e < 48 * 16; e += 256) {    // RoPE Q (pos q0+iq) + round
    int iq = e >> 4, i = e & 15;
    float sn, cs; sincosf((float)(q0 + iq) * c_invfreq[i], &sn, &cs);
    float ev = Q[iq][2*i], ov = Q[iq][2*i+1];
    Q[iq][2*i] = tf32r(ev * cs - ov * sn); Q[iq][2*i+1] = tf32r(ev * sn + ov * cs);
  }
  __syncthreads();

  const float scale = 0.17677669529663687f;
  if (w < 6) {                                // scores 48x96: wm 0..2, wn 0..1
    const int wm = w >> 1, wn = w & 1;
    const int m0 = wm * 16;
    float c_[6][4];
#pragma unroll
    for (int jn = 0; jn < 6; jn++)
#pragma unroll
      for (int r = 0; r < 4; r++) c_[jn][r] = 0.f;
#pragma unroll
    for (int ks = 0; ks < 32; ks += 8) {
      unsigned ar[4];
      ar[0] = __float_as_uint(Q[m0 + g    ][ks + tq    ]);
      ar[1] = __float_as_uint(Q[m0 + g + 8][ks + tq    ]);
      ar[2] = __float_as_uint(Q[m0 + g    ][ks + tq + 4]);
      ar[3] = __float_as_uint(Q[m0 + g + 8][ks + tq + 4]);
#pragma unroll
      for (int jn = 0; jn < 6; jn++) {
        int n0 = wn * 48 + jn * 8;
        unsigned br[2];
        br[0] = __float_as_uint(K[n0 + g][ks + tq    ]);
        br[1] = __float_as_uint(K[n0 + g][ks + tq + 4]);
        mma_tf32(c_[jn], ar, br);
      }
    }
#pragma unroll
    for (int jn = 0; jn < 6; jn++) {
      int col = wn * 48 + jn * 8 + 2 * tq;
      float kb0 = kbias[col], kb1 = kbias[col + 1];
      *(float2*)&P[m0 + g    ][col] = make_float2(c_[jn][0] * scale + kb0, c_[jn][1] * scale + kb1);
      *(float2*)&P[m0 + g + 8][col] = make_float2(c_[jn][2] * scale + kb0, c_[jn][3] * scale + kb1);
    }
  }
  __syncthreads();

#pragma unroll
  for (int i = 0; i < 3; i++) {               // V -> Vt (aliases K)
    int e = t + i * 256;
    int r = e >> 3, d4 = (e & 7) * 4;
    float4 v4 = *(const float4*)(qkv + (tokbase + (size_t)r * 64) * 768 + 512 + h * 32 + d4);
    VT[(d4 + 0) * 100 + r] = tf32r(v4.x); VT[(d4 + 1) * 100 + r] = tf32r(v4.y);
    VT[(d4 + 2) * 100 + r] = tf32r(v4.z); VT[(d4 + 3) * 100 + r] = tf32r(v4.w);
  }
#pragma unroll
  for (int rr = 0; rr < 6; rr++) {            // softmax 48 rows / 8 warps
    int r = w * 6 + rr;
    float x0 = P[r][lane], x1 = P[r][lane + 32], x2 = P[r][lane + 64];
    float mx = fmaxf(x0, fmaxf(x1, x2));
#pragma unroll
    for (int o = 16; o > 0; o >>= 1) mx = fmaxf(mx, __shfl_xor_sync(0xffffffffu, mx, o));
    float e0 = __expf(x0 - mx), e1 = __expf(x1 - mx), e2 = __expf(x2 - mx);
    float sm = e0 + e1 + e2;
#pragma unroll
    for (int o = 16; o > 0; o >>= 1) sm += __shfl_xor_sync(0xffffffffu, sm, o);
    float inv = 1.f / sm;
    P[r][lane] = tf32r(e0 * inv); P[r][lane + 32] = tf32r(e1 * inv); P[r][lane + 64] = tf32r(e2 * inv);
  }
  __syncthreads();

  if (w < 6) {                                // AV: P(48x96) x Vt(32x96)
    const int wm = w >> 1, wn = w & 1;
    const int m0 = wm * 16;
    float o_[2][4];
#pragma unroll
    for (int jn = 0; jn < 2; jn++)
#pragma unroll
      for (int r = 0; r < 4; r++) o_[jn][r] = 0.f;
#pragma unroll
    for (int ks = 0; ks < 96; ks += 8) {
      unsigned ar[4];
      ar[0] = __float_as_uint(P[m0 + g    ][ks + tq    ]);
      ar[1] = __float_as_uint(P[m0 + g + 8][ks + tq    ]);
      ar[2] = __float_as_uint(P[m0 + g    ][ks + tq + 4]);
      ar[3] = __float_as_uint(P[m0 + g + 8][ks + tq + 4]);
#pragma unroll
      for (int jn = 0; jn < 2; jn++) {
        int n0 = wn * 16 + jn * 8;
        unsigned br[2];
        br[0] = __float_as_uint(VT[(n0 + g) * 100 + ks + tq    ]);
        br[1] = __float_as_uint(VT[(n0 + g) * 100 + ks + tq + 4]);
        mma_tf32(o_[jn], ar, br);
      }
    }
    size_t row0 = tokbase + (size_t)(q0 + m0 + g) * 64;
    size_t row1 = tokbase + (size_t)(q0 + m0 + g + 8) * 64;
#pragma unroll
    for (int jn = 0; jn < 2; jn++) {
      int col = h * 32 + wn * 16 + jn * 8 + 2 * tq;
      *(float2*)&out[row0 * 256 + col] = make_float2(o_[jn][0], o_[jn][1]);
      *(float2*)&out[row1 * 256 + col] = make_float2(o_[jn][2], o_[jn][3]);
    }
  }
}

// ---------------- stage-2 qry attention (mma): per (b2, h): 32 q, 96 keys -------
__global__ __launch_bounds__(256)
void att2_qry_kernel(const float* __restrict__ qkv, const float* __restrict__ kv2,
                     const int* __restrict__ mask, float* __restrict__ out)
{
  __shared__ float Q[32][36], K[96][36], P[32][100];
  __shared__ float kbias[96];
  float* VT = &K[0][0];                 // Vt[d][j] = VT[d*100 + j]
  const int blk = blockIdx.x;
  const int h = blk & 7, b2 = blk >> 3;
  const int b = b2 >> 6, c = b2 & 63;
  const int t = threadIdx.x;
  const size_t tokbase = (size_t)b * 8192 + c;
  const size_t kvbase = (size_t)b2 * 96 * 512 + h * 32;
  const int w = t >> 5, lane = t & 31;
  const int g = lane >> 2, tq = lane & 3;

  {                                           // Q: 32x32 (one f4 per thread)
    int iq = t >> 3, d4 = (t & 7) * 4;
    *(float4*)&Q[iq][d4] = *(const float4*)(qkv + (tokbase + (size_t)(96 + iq) * 64) * 768 + h * 32 + d4);
  }
#pragma unroll
  for (int i = 0; i < 3; i++) {               // K2: 96x32
    int e = t + i * 256;
    int r = e >> 3, d4 = (e & 7) * 4;
    *(float4*)&K[r][d4] = *(const float4*)(kv2 + kvbase + (size_t)r * 512 + d4);
  }
  if (t < 96) kbias[t] = (mask[b * 128 + t] > 0) ? 0.f : -1e9f;
  __syncthreads();
  for (int e = t; e < 96 * 16; e += 256) {    // RoPE K (pos r) + round
    int r = e >> 4, i = e & 15;
    float sn, cs; sincosf((float)r * c_invfreq[i], &sn, &cs);
    float ev = K[r][2*i], ov = K[r][2*i+1];
    K[r][2*i] = tf32r(ev * cs - ov * sn); K[r][2*i+1] = tf32r(ev * sn + ov * cs);
  }
  for (int e = t; e < 32 * 16; e += 256) {    // RoPE Q (pos 96+iq) + round
    int iq = e >> 4, i = e & 15;
    float sn, cs; sincosf((float)(96 + iq) * c_invfreq[i], &sn, &cs);
    float ev = Q[iq][2*i], ov = Q[iq][2*i+1];
    Q[iq][2*i] = tf32r(ev * cs - ov * sn); Q[iq][2*i+1] = tf32r(ev * sn + ov * cs);
  }
  __syncthreads();

  const float scale = 0.17677669529663687f;
  {                                           // scores 32x96: wm = w&1, wn = w>>1
    const int wm = w & 1, wn = w >> 1;
    const int m0 = wm * 16;
    float c_[3][4];
#pragma unroll
    for (int jn = 0; jn < 3; jn++)
#pragma unroll
      for (int r = 0; r < 4; r++) c_[jn][r] = 0.f;
#pragma unroll
    for (int ks = 0; ks < 32; ks += 8) {
      unsigned ar[4];
      ar[0] = __float_as_uint(Q[m0 + g    ][ks + tq    ]);
      ar[1] = __float_as_uint(Q[m0 + g + 8][ks + tq    ]);
      ar[2] = __float_as_uint(Q[m0 + g    ][ks + tq + 4]);
      ar[3] = __float_as_uint(Q[m0 + g + 8][ks + tq + 4]);
#pragma unroll
      for (int jn = 0; jn < 3; jn++) {
        int n0 = wn * 24 + jn * 8;
        unsigned br[2];
        br[0] = __float_as_uint(K[n0 + g][ks + tq    ]);
        br[1] = __float_as_uint(K[n0 + g][ks + tq + 4]);
        mma_tf32(c_[jn], ar, br);
      }
    }
#pragma unroll
    for (int jn = 0; jn < 3; jn++) {
      int col = wn * 24 + jn * 8 + 2 * tq;
      float kb0 = kbias[col], kb1 = kbias[col + 1];
      *(float2*)&P[m0 + g    ][col] = make_float2(c_[jn][0] * scale + kb0, c_[jn][1] * scale + kb1);
      *(float2*)&P[m0 + g + 8][col] = make_float2(c_[jn][2] * scale + kb0, c_[jn][3] * scale + kb1);
    }
  }
  __syncthreads();

#pragma unroll
  for (int i = 0; i < 3; i++) {               // V2 -> Vt (aliases K)
    int e = t + i * 256;
    int r = e >> 3, d4 = (e & 7) * 4;
    float4 v4 = *(const float4*)(kv2 + kvbase + (size_t)r * 512 + 256 + d4);
    VT[(d4 + 0) * 100 + r] = tf32r(v4.x); VT[(d4 + 1) * 100 + r] = tf32r(v4.y);
    VT[(d4 + 2) * 100 + r] = tf32r(v4.z); VT[(d4 + 3) * 100 + r] = tf32r(v4.w);
  }
#pragma unroll
  for (int rr = 0; rr < 4; rr++) {            // softmax 32 rows / 8 warps
    int r = w * 4 + rr;
    float x0 = P[r][lane], x1 = P[r][lane + 32], x2 = P[r][lane + 64];
    float mx = fmaxf(x0, fmaxf(x1, x2));
#pragma unroll
    for (int o = 16; o > 0; o >>= 1) mx = fmaxf(mx, __shfl_xor_sync(0xffffffffu, mx, o));
    float e0 = __expf(x0 - mx), e1 = __expf(x1 - mx), e2 = __expf(x2 - mx);
    float sm = e0 + e1 + e2;
#pragma unroll
    for (int o = 16; o > 0; o >>= 1) sm += __shfl_xor_sync(0xffffffffu, sm, o);
    float inv = 1.f / sm;
    P[r][lane] = tf32r(e0 * inv); P[r][lane + 32] = tf32r(e1 * inv); P[r][lane + 64] = tf32r(e2 * inv);
  }
  __syncthreads();

  {                                           // AV: P(32x96) x Vt(32x96)
    const int wm = w & 1, wn = w >> 1;
    const int m0 = wm * 16;
    const int n0 = wn * 8;
    float o_[4];
#pragma unroll
    for (int r = 0; r < 4; r++) o_[r] = 0.f;
#pragma unroll
    for (int ks = 0; ks < 96; ks += 8) {
      unsigned ar[4], br[2];
      ar[0] = __float_as_uint(P[m0 + g    ][ks + tq    ]);
      ar[1] = __float_as_uint(P[m0 + g + 8][ks + tq    ]);
      ar[2] = __float_as_uint(P[m0 + g    ][ks + tq + 4]);
      ar[3] = __float_as_uint(P[m0 + g + 8][ks + tq + 4]);
      br[0] = __float_as_uint(VT[(n0 + g) * 100 + ks + tq    ]);
      br[1] = __float_as_uint(VT[(n0 + g) * 100 + ks + tq + 4]);
      mma_tf32(o_, ar, br);
    }
    size_t row0 = tokbase + (size_t)(96 + m0 + g) * 64;
    size_t row1 = tokbase + (size_t)(96 + m0 + g + 8) * 64;
    int col = h * 32 + n0 + 2 * tq;
    *(float2*)&out[row0 * 256 + col] = make_float2(o_[0], o_[1]);
    *(float2*)&out[row1 * 256 + col] = make_float2(o_[2], o_[3]);
  }
}

// ---------------- LayerNorm over E=256 (one warp per row) ----------------
__global__ __launch_bounds__(256)
void ln_kernel(const float* __restrict__ x, const float* __restrict__ g,
               const float* __restrict__ bb, float* __restrict__ y)
{
  const int w = threadIdx.x >> 5, lane = threadIdx.x & 31;
  const size_t row = (size_t)blockIdx.x * 8 + w;
  const float* xr = x + row * 256 + lane * 8;
  float4 v0 = *(const float4*)xr;
  float4 v1 = *(const float4*)(xr + 4);
  float s = v0.x+v0.y+v0.z+v0.w + v1.x+v1.y+v1.z+v1.w;
#pragma unroll
  for (int o = 16; o > 0; o >>= 1) s += __shfl_xor_sync(0xffffffffu, s, o);
  float mean = s * 0.00390625f;
  float d0=v0.x-mean, d1=v0.y-mean, d2=v0.z-mean, d3=v0.w-mean;
  float d4=v1.x-mean, d5=v1.y-mean, d6=v1.z-mean, d7=v1.w-mean;
  float q = d0*d0+d1*d1+d2*d2+d3*d3+d4*d4+d5*d5+d6*d6+d7*d7;
#pragma unroll
  for (int o = 16; o > 0; o >>= 1) q += __shfl_xor_sync(0xffffffffu, q, o);
  float rstd = rsqrtf(q * 0.00390625f + 1e-5f);
  const float* gp = g + lane * 8; const float* bp = bb + lane * 8;
  float4 g0 = *(const float4*)gp, g1 = *(const float4*)(gp + 4);
  float4 b0 = *(const float4*)bp, b1 = *(const float4*)(bp + 4);
  float* yr = y + row * 256 + lane * 8;
  *(float4*)yr       = make_float4(d0*rstd*g0.x+b0.x, d1*rstd*g0.y+b0.y,
                                   d2*rstd*g0.z+b0.z, d3*rstd*g0.w+b0.w);
  *(float4*)(yr + 4) = make_float4(d4*rstd*g1.x+b1.x, d5*rstd*g1.y+b1.y,
                                   d6*rstd*g1.z+b1.z, d7*rstd*g1.w+b1.w);
}

// ---------------- nan_to_num ----------------
__global__ void nan2num_kernel(const float* __restrict__ in, float* __restrict__ out)
{
  size_t i = (size_t)blockIdx.x * blockDim.x + threadIdx.x;
  float4 v = ((const float4*)in)[i];
  v.x = isfinite(v.x) ? v.x : 0.f;
  v.y = isfinite(v.y) ? v.y : 0.f;
  v.z = isfinite(v.z) ? v.z : 0.f;
  v.w = isfinite(v.w) ? v.w : 0.f;
  ((float4*)out)[i] = v;
}

// ---------------- launch ----------------
extern "C" void kernel_launch(void* const* d_in, const int* in_sizes, int n_in,
                              void* d_out, int out_size)
{
  const float* src  = (const float*)d_in[0];
  const int*   mask = (const int*)d_in[1];
  int base = (in_sizes[2] == 1) ? 3 : 2;
  const float* y_in_w  = (const float*)d_in[base + 0];
  const float* y_in_b  = (const float*)d_in[base + 1];
  const float* y_out_w = (const float*)d_in[base + 2];
  const float* y_out_b = (const float*)d_in[base + 3];
  const float* x_in_w  = (const float*)d_in[base + 4];
  const float* x_in_b  = (const float*)d_in[base + 5];
  const float* x_out_w = (const float*)d_in[base + 6];
  const float* x_out_b = (const float*)d_in[base + 7];
  const float* w1  = (const float*)d_in[base + 8];
  const float* b1  = (const float*)d_in[base + 9];
  const float* w2  = (const float*)d_in[base + 10];
  const float* b2  = (const float*)d_in[base + 11];
  const float* n1g = (const float*)d_in[base + 12];
  const float* n1b = (const float*)d_in[base + 13];
  const float* n2g = (const float*)d_in[base + 14];
  const float* n2b = (const float*)d_in[base + 15];
  const float* n3g = (const float*)d_in[base + 16];
  const float* n3b = (const float*)d_in[base + 17];
  float* out = (float*)d_out;

  float *x0, *qkvb, *attb, *xnb, *yb, *kv2b, *zb, *hb;
  cudaGetSymbolAddress((void**)&x0,   g_x0);
  cudaGetSymbolAddress((void**)&qkvb, g_qkv);
  cudaGetSymbolAddress((void**)&attb, g_att);
  cudaGetSymbolAddress((void**)&xnb,  g_xn);
  cudaGetSymbolAddress((void**)&yb,   g_y);
  cudaGetSymbolAddress((void**)&kv2b, g_kv2);
  cudaGetSymbolAddress((void**)&zb,   g_z);
  cudaGetSymbolAddress((void**)&hb,   g_h);

  // Stage 1: row-axis self-attention + residual + LN1
  nan2num_kernel<<<16384, 256>>>(src, x0);
  gemm_tf32<MAP_ID, MAP_ID, EPI_B  ><<<dim3(6, 512), 256>>>(x0, y_in_w, y_in_b, qkvb, nullptr, 65536, 768, 256);
  att1_kernel<<<8192, 256>>>(qkvb, attb);
  gemm_tf32<MAP_ID, MAP_ID, EPI_RES><<<dim3(2, 512), 256>>>(attb, y_out_w, y_out_b, yb, x0, 65536, 256, 256);
  ln_kernel<<<8192, 256>>>(yb, n1g, n1b, xnb);

  // Stage 2: column-axis attention with RoPE + key-padding mask
  gemm_tf32<MAP_ID, MAP_ID, EPI_B  ><<<dim3(6, 512), 256>>>(xnb, x_in_w, x_in_b, qkvb, nullptr, 65536, 768, 256);
  att2_ctx_kernel<<<8192, 256>>>(qkvb, mask, attb);
  gemm_tf32<MAP_CTX, MAP_CTX, EPI_RES><<<dim3(2, 384), 256>>>(attb, x_out_w, x_out_b, yb, xnb, 49152, 256, 256);
  gemm_tf32<MAP_CTX, MAP_ID,  EPI_B  ><<<dim3(4, 384), 256>>>(yb, x_in_w + 256 * 256, x_in_b + 256, kv2b, nullptr, 49152, 512, 256);
  att2_qry_kernel<<<4096, 256>>>(qkvb, kv2b, mask, attb);
  gemm_tf32<MAP_QRY, MAP_QRY, EPI_RES><<<dim3(2, 128), 256>>>(attb, x_out_w, x_out_b, yb, xnb, 16384, 256, 256);

  // LN2 + MLP + residual + LN3
  ln_kernel<<<8192, 256>>>(yb, n2g, n2b, zb);
  gemm_tf32<MAP_ID, MAP_ID, EPI_GELU><<<dim3(8, 512), 256>>>(zb, w1, b1, hb, nullptr, 65536, 1024, 256);
  gemm_tf32<MAP_ID, MAP_ID, EPI_RES ><<<dim3(2, 512), 256>>>(hb, w2, b2, x0, zb, 65536, 256, 1024);
  ln_kernel<<<8192, 256>>>(x0, n3g, n3b, out);
}

// round 14
// speedup vs baseline: 2.7498x; 1.0272x over previous
#include <cuda_runtime.h>
#include <cuda_bf16.h>
#include <math.h>

// ---------------- static problem dims ----------------
// src: (8, 128, 64, 256). Token n = (b*128 + r)*64 + c  = b*8192 + r*64 + c
#define NTOK 65536
#define EDIM 256

// ---------------- scratch (device globals; no allocations) ----------------
__device__ float g_x0 [(size_t)NTOK * 256];      // MLP output scratch
__device__ float g_qkv[(size_t)NTOK * 768];
__device__ float g_att[(size_t)NTOK * 256];
__device__ float g_xn [(size_t)NTOK * 256];
__device__ float g_y  [(size_t)NTOK * 256];
__device__ float g_kv2[(size_t)512 * 96 * 512];
__device__ float g_z  [(size_t)NTOK * 256];
__device__ float g_h  [(size_t)NTOK * 1024];
__device__ float2 g_rope[128 * 16];              // (cos, sin) per (pos, freq)

__constant__ float c_invfreq[16] = {
  1.0f, 0.5623413251903491f, 0.31622776601683794f, 0.17782794100389228f,
  0.1f, 0.05623413251903491f, 0.031622776601683794f, 0.017782794100389228f,
  0.01f, 0.005623413251903491f, 0.0031622776601683794f, 0.0017782794100389229f,
  0.001f, 0.0005623413251903491f, 0.00031622776601683794f, 0.00017782794100389227f
};

enum { MAP_ID = 0, MAP_CTX = 1, MAP_QRY = 2 };
enum { EPI_B = 0, EPI_RES = 1, EPI_GELU = 2 };

template<int MAP>
__device__ __forceinline__ int map_row(int m) {
  if (MAP == MAP_ID) {
    return m;
  } else if (MAP == MAP_CTX) {            // m = b2*96 + r,  r in [0,96)
    int b2 = m / 96, r = m - b2 * 96;
    int b = b2 >> 6, c = b2 & 63;
    return b * 8192 + r * 64 + c;
  } else {                                 // m = b2*32 + i,  r = 96 + i
    int b2 = m >> 5, i = m & 31;
    int b = b2 >> 6, c = b2 & 63;
    return b * 8192 + (96 + i) * 64 + c;
  }
}

__device__ __forceinline__ float tf32r(float x) {
  float y;
  asm("cvt.rna.tf32.f32 %0, %1;" : "=f"(y) : "f"(x));
  return y;
}

__device__ __forceinline__ float sanf(float x) { return isfinite(x) ? x : 0.f; }

__device__ __forceinline__ float gelu_t(float x) {
  // tanh-form GELU with HW tanh.approx (exact-erf deviation <= ~5e-4 abs)
  float x2 = x * x;
  float tt = x * fmaf(0.035677408136300125f, x2, 0.7978845608028654f);
  float th;
  asm("tanh.approx.f32 %0, %1;" : "=f"(th) : "f"(tt));
  float hx = 0.5f * x;
  return fmaf(hx, th, hx);
}

__device__ __forceinline__ void mma_tf32(float c[4], const unsigned a[4], const unsigned b[2]) {
  asm volatile(
    "mma.sync.aligned.m16n8k8.row.col.f32.tf32.tf32.f32 "
    "{%0,%1,%2,%3}, {%4,%5,%6,%7}, {%8,%9}, {%0,%1,%2,%3};\n"
    : "+f"(c[0]), "+f"(c[1]), "+f"(c[2]), "+f"(c[3])
    : "r"(a[0]), "r"(a[1]), "r"(a[2]), "r"(a[3]), "r"(b[0]), "r"(b[1]));
}

// ---------------- RoPE table init (2048 sincosf total) ----------------
__global__ void rope_table_kernel() {
  int i = threadIdx.x + blockIdx.x * blockDim.x;   // 0..2047
  int r = i >> 4, f = i & 15;
  float sn, cs;
  sincosf((float)r * c_invfreq[f], &sn, &cs);
  g_rope[i] = make_float2(cs, sn);
}

// ---------------- TF32 NT GEMM: C[M,N] = A[M,K] . W[N,K]^T + bias (+epi) ------
template<int MAPA, int MAPC, int EPI, int SANA, int SANR>
__global__ __launch_bounds__(256, 2)
void gemm_tf32(const float* __restrict__ A, const float* __restrict__ W,
               const float* __restrict__ bias, float* __restrict__ C,
               const float* __restrict__ Res, int M, int N, int K)
{
  __shared__ float As[2][128][20];
  __shared__ float Bs[2][128][20];
  const int t  = threadIdx.x;
  const int mt = blockIdx.y * 128;
  const int nt = blockIdx.x * 128;
  const int lm = t >> 2;
  const int lk = (t & 3) << 2;

  const int arow0 = map_row<MAPA>(mt + lm);
  const int arow1 = map_row<MAPA>(mt + lm + 64);
  const float* Ap0 = A + (size_t)arow0 * K + lk;
  const float* Ap1 = A + (size_t)arow1 * K + lk;
  const float* Wp0 = W + (size_t)(nt + lm) * K + lk;
  const float* Wp1 = W + (size_t)(nt + lm + 64) * K + lk;

  const int w = t >> 5, lane = t & 31;
  const int wm = w & 1, wn = w >> 1;
  const int g = lane >> 2, tq = lane & 3;

  float acc[4][4][4];
#pragma unroll
  for (int i = 0; i < 4; i++)
#pragma unroll
    for (int j = 0; j < 4; j++)
#pragma unroll
      for (int r = 0; r < 4; r++) acc[i][j][r] = 0.f;

  float4 sa0 = *(const float4*)Ap0;
  float4 sa1 = *(const float4*)Ap1;
  float4 sb0 = *(const float4*)Wp0;
  float4 sb1 = *(const float4*)Wp1;

  int buf = 0;
  for (int k0 = 0; k0 < K; k0 += 16) {
    if (SANA) {
      sa0.x = sanf(sa0.x); sa0.y = sanf(sa0.y); sa0.z = sanf(sa0.z); sa0.w = sanf(sa0.w);
      sa1.x = sanf(sa1.x); sa1.y = sanf(sa1.y); sa1.z = sanf(sa1.z); sa1.w = sanf(sa1.w);
    }
    *(float4*)&As[buf][lm][lk]      = make_float4(tf32r(sa0.x), tf32r(sa0.y), tf32r(sa0.z), tf32r(sa0.w));
    *(float4*)&As[buf][lm + 64][lk] = make_float4(tf32r(sa1.x), tf32r(sa1.y), tf32r(sa1.z), tf32r(sa1.w));
    *(float4*)&Bs[buf][lm][lk]      = make_float4(tf32r(sb0.x), tf32r(sb0.y), tf32r(sb0.z), tf32r(sb0.w));
    *(float4*)&Bs[buf][lm + 64][lk] = make_float4(tf32r(sb1.x), tf32r(sb1.y), tf32r(sb1.z), tf32r(sb1.w));
    __syncthreads();
    if (k0 + 16 < K) {
      sa0 = *(const float4*)(Ap0 + k0 + 16);
      sa1 = *(const float4*)(Ap1 + k0 + 16);
      sb0 = *(const float4*)(Wp0 + k0 + 16);
      sb1 = *(const float4*)(Wp1 + k0 + 16);
    }
#pragma unroll
    for (int ks = 0; ks < 16; ks += 8) {
      unsigned ar[4][4], br[4][2];
#pragma unroll
      for (int im = 0; im < 4; im++) {
        int m = wm * 64 + im * 16;
        ar[im][0] = __float_as_uint(As[buf][m + g    ][ks + tq    ]);
        ar[im][1] = __float_as_uint(As[buf][m + g + 8][ks + tq    ]);
        ar[im][2] = __float_as_uint(As[buf][m + g    ][ks + tq + 4]);
        ar[im][3] = __float_as_uint(As[buf][m + g + 8][ks + tq + 4]);
      }
#pragma unroll
      for (int jn = 0; jn < 4; jn++) {
        int n = wn * 32 + jn * 8;
        br[jn][0] = __float_as_uint(Bs[buf][n + g][ks + tq    ]);
        br[jn][1] = __float_as_uint(Bs[buf][n + g][ks + tq + 4]);
      }
#pragma unroll
      for (int im = 0; im < 4; im++)
#pragma unroll
        for (int jn = 0; jn < 4; jn++)
          mma_tf32(acc[im][jn], ar[im], br[jn]);
    }
    buf ^= 1;
  }

#pragma unroll
  for (int im = 0; im < 4; im++) {
    int r0 = mt + wm * 64 + im * 16 + g;
    int cr0 = map_row<MAPC>(r0);
    int cr1 = map_row<MAPC>(r0 + 8);
#pragma unroll
    for (int jn = 0; jn < 4; jn++) {
      int n = nt + wn * 32 + jn * 8 + 2 * tq;
      float2 bv = *(const float2*)&bias[n];
      float o0 = acc[im][jn][0] + bv.x, o1 = acc[im][jn][1] + bv.y;
      float o2 = acc[im][jn][2] + bv.x, o3 = acc[im][jn][3] + bv.y;
      if (EPI == EPI_RES) {
        float2 v0 = *(const float2*)&Res[(size_t)cr0 * N + n];
        float2 v1 = *(const float2*)&Res[(size_t)cr1 * N + n];
        if (SANR) {
          v0.x = sanf(v0.x); v0.y = sanf(v0.y); v1.x = sanf(v1.x); v1.y = sanf(v1.y);
        }
        o0 += v0.x; o1 += v0.y; o2 += v1.x; o3 += v1.y;
      }
      if (EPI == EPI_GELU) {
        o0 = gelu_t(o0); o1 = gelu_t(o1); o2 = gelu_t(o2); o3 = gelu_t(o3);
      }
      *(float2*)&C[(size_t)cr0 * N + n] = make_float2(o0, o1);
      *(float2*)&C[(size_t)cr1 * N + n] = make_float2(o2, o3);
    }
  }
}

// ---------------- stage-1 attention (mma): per (b1, h), L=64, hd=32 ----------
__global__ __launch_bounds__(256)
void att1_kernel(const float* __restrict__ qkv, float* __restrict__ out)
{
  __shared__ float Q[64][36], K[64][36], Vt[32][68], P[64][68];
  const int blk = blockIdx.x;
  const int b1 = blk >> 3, h = blk & 7;
  const int t = threadIdx.x;
  const size_t base = (size_t)b1 * 64 * 768 + h * 32;
  const int w = t >> 5, lane = t & 31;
  const int g = lane >> 2, tq = lane & 3;

#pragma unroll
  for (int i = 0; i < 2; i++) {
    int e = t + i * 256;
    int c = e >> 3, d4 = (e & 7) * 4;
    size_t o = base + (size_t)c * 768 + d4;
    float4 q4 = *(const float4*)(qkv + o);
    float4 k4 = *(const float4*)(qkv + o + 256);
    float4 v4 = *(const float4*)(qkv + o + 512);
    *(float4*)&Q[c][d4] = make_float4(tf32r(q4.x), tf32r(q4.y), tf32r(q4.z), tf32r(q4.w));
    *(float4*)&K[c][d4] = make_float4(tf32r(k4.x), tf32r(k4.y), tf32r(k4.z), tf32r(k4.w));
    Vt[d4 + 0][c] = tf32r(v4.x); Vt[d4 + 1][c] = tf32r(v4.y);
    Vt[d4 + 2][c] = tf32r(v4.z); Vt[d4 + 3][c] = tf32r(v4.w);
  }
  __syncthreads();

  const float scale = 0.17677669529663687f;   // 1/sqrt(32)
  {
    const int wm = w >> 1, wn = w & 1;
    const int m0 = wm * 16;
    float c_[4][4];
#pragma unroll
    for (int jn = 0; jn < 4; jn++)
#pragma unroll
      for (int r = 0; r < 4; r++) c_[jn][r] = 0.f;
#pragma unroll
    for (int ks = 0; ks < 32; ks += 8) {
      unsigned ar[4];
      ar[0] = __float_as_uint(Q[m0 + g    ][ks + tq    ]);
      ar[1] = __float_as_uint(Q[m0 + g + 8][ks + tq    ]);
      ar[2] = __float_as_uint(Q[m0 + g    ][ks + tq + 4]);
      ar[3] = __float_as_uint(Q[m0 + g + 8][ks + tq + 4]);
#pragma unroll
      for (int jn = 0; jn < 4; jn++) {
        int n0 = wn * 32 + jn * 8;
        unsigned br[2];
        br[0] = __float_as_uint(K[n0 + g][ks + tq    ]);
        br[1] = __float_as_uint(K[n0 + g][ks + tq + 4]);
        mma_tf32(c_[jn], ar, br);
      }
    }
#pragma unroll
    for (int jn = 0; jn < 4; jn++) {
      int col = wn * 32 + jn * 8 + 2 * tq;
      *(float2*)&P[m0 + g    ][col] = make_float2(c_[jn][0] * scale, c_[jn][1] * scale);
      *(float2*)&P[m0 + g + 8][col] = make_float2(c_[jn][2] * scale, c_[jn][3] * scale);
    }
  }
  __syncthreads();

#pragma unroll
  for (int rr = 0; rr < 8; rr++) {
    int r = w * 8 + rr;
    float a = P[r][lane], b = P[r][lane + 32];
    float mx = fmaxf(a, b);
#pragma unroll
    for (int o = 16; o > 0; o >>= 1) mx = fmaxf(mx, __shfl_xor_sync(0xffffffffu, mx, o));
    float ea = __expf(a - mx), eb = __expf(b - mx);
    float sm = ea + eb;
#pragma unroll
    for (int o = 16; o > 0; o >>= 1) sm += __shfl_xor_sync(0xffffffffu, sm, o);
    float inv = 1.f / sm;
    P[r][lane] = tf32r(ea * inv); P[r][lane + 32] = tf32r(eb * inv);
  }
  __syncthreads();

  {
    const int wm = w >> 1, wn = w & 1;
    const int m0 = wm * 16;
    float o_[2][4];
#pragma unroll
    for (int jn = 0; jn < 2; jn++)
#pragma unroll
      for (int r = 0; r < 4; r++) o_[jn][r] = 0.f;
#pragma unroll
    for (int ks = 0; ks < 64; ks += 8) {
      unsigned ar[4];
      ar[0] = __float_as_uint(P[m0 + g    ][ks + tq    ]);
      ar[1] = __float_as_uint(P[m0 + g + 8][ks + tq    ]);
      ar[2] = __float_as_uint(P[m0 + g    ][ks + tq + 4]);
      ar[3] = __float_as_uint(P[m0 + g + 8][ks + tq + 4]);
#pragma unroll
      for (int jn = 0; jn < 2; jn++) {
        int n0 = wn * 16 + jn * 8;
        unsigned br[2];
        br[0] = __float_as_uint(Vt[n0 + g][ks + tq    ]);
        br[1] = __float_as_uint(Vt[n0 + g][ks + tq + 4]);
        mma_tf32(o_[jn], ar, br);
      }
    }
    int row0 = b1 * 64 + m0 + g;
#pragma unroll
    for (int jn = 0; jn < 2; jn++) {
      int col = h * 32 + wn * 16 + jn * 8 + 2 * tq;
      *(float2*)&out[(size_t)row0 * 256 + col]       = make_float2(o_[jn][0], o_[jn][1]);
      *(float2*)&out[(size_t)(row0 + 8) * 256 + col] = make_float2(o_[jn][2], o_[jn][3]);
    }
  }
}

// ---------------- stage-2 ctx attention (mma): per (b2,h,half): 48 q, 96 keys ----
__global__ __launch_bounds__(256)
void att2_ctx_kernel(const float* __restrict__ qkv, const int* __restrict__ mask,
                     float* __restrict__ out)
{
  __shared__ float Q[48][36], K[96][36], P[48][100];
  __shared__ float kbias[96];
  float* VT = &K[0][0];                 // Vt[d][j] = VT[d*100 + j]; 3200 <= 3456
  const int blk = blockIdx.x;
  const int half = blk & 1, h = (blk >> 1) & 7, b2 = blk >> 4;
  const int b = b2 >> 6, c = b2 & 63;
  const int t = threadIdx.x;
  const int q0 = half * 48;
  const size_t tokbase = (size_t)b * 8192 + c;
  const int w = t >> 5, lane = t & 31;
  const int g = lane >> 2, tq = lane & 3;

  for (int e = t; e < 384; e += 256) {        // Q: 48x32 (raw; rounded post-RoPE)
    int iq = e >> 3, d4 = (e & 7) * 4;
    *(float4*)&Q[iq][d4] = *(const float4*)(qkv + (tokbase + (size_t)(q0 + iq) * 64) * 768 + h * 32 + d4);
  }
#pragma unroll
  for (int i = 0; i < 3; i++) {               // K: 96x32
    int e = t + i * 256;
    int r = e >> 3, d4 = (e & 7) * 4;
    *(float4*)&K[r][d4] = *(const float4*)(qkv + (tokbase + (size_t)r * 64) * 768 + 256 + h * 32 + d4);
  }
  if (t < 96) kbias[t] = (mask[b * 128 + t] > 0) ? 0.f : -1e9f;
  __syncthreads();
  for (int e = t; e < 96 * 16; e += 256) {    // RoPE K (pos r) via table + round
    int r = e >> 4, i = e & 15;
    float2 t2 = __ldg(&g_rope[e]);            // e == r*16 + i
    float ev = K[r][2*i], ov = K[r][2*i+1];
    K[r][2*i] = tf32r(ev * t2.x - ov * t2.y); K[r][2*i+1] = tf32r(ev * t2.y + ov * t2.x);
  }
  for (int e = t; e < 48 * 16; e += 256) {    // RoPE Q (pos q0+iq) via table + round
    int iq = e >> 4, i = e & 15;
    float2 t2 = __ldg(&g_rope[e + q0 * 16]);
    float ev = Q[iq][2*i], ov = Q[iq][2*i+1];
    Q[iq][2*i] = tf32r(ev * t2.x - ov * t2.y); Q[iq][2*i+1] = tf32r(ev * t2.y + ov * t2.x);
  }
  __syncthreads();

  const float scale = 0.17677669529663687f;
  if (w < 6) {                                // scores 48x96: wm 0..2, wn 0..1
    const int wm = w >> 1, wn = w & 1;
    const int m0 = wm * 16;
    float c_[6][4];
#pragma unroll
    for (int jn = 0; jn < 6; jn++)
#pragma unroll
      for (int r = 0; r < 4; r++) c_[jn][r] = 0.f;
#pragma unroll
    for (int ks = 0; ks < 32; ks += 8) {
      unsigned ar[4];
      ar[0] = __float_as_uint(Q[m0 + g    ][ks + tq    ]);
      ar[1] = __float_as_uint(Q[m0 + g + 8][ks + tq    ]);
      ar[2] = __float_as_uint(Q[m0 + g    ][ks + tq + 4]);
      ar[3] = __float_as_uint(Q[m0 + g + 8][ks + tq + 4]);
#pragma unroll
      for (int jn = 0; jn < 6; jn++) {
        int n0 = wn * 48 + jn * 8;
        unsigned br[2];
        br[0] = __float_as_uint(K[n0 + g][ks + tq    ]);
        br[1] = __float_as_uint(K[n0 + g][ks + tq + 4]);
        mma_tf32(c_[jn], ar, br);
      }
    }
#pragma unroll
    for (int jn = 0; jn < 6; jn++) {
      int col = wn * 48 + jn * 8 + 2 * tq;
      float kb0 = kbias[col], kb1 = kbias[col + 1];
      *(float2*)&P[m0 + g    ][col] = make_float2(c_[jn][0] * scale + kb0, c_[jn][1] * scale + kb1);
      *(float2*)&P[m0 + g + 8][col] = make_float2(c_[jn][2] * scale + kb0, c_[jn][3] * scale + kb1);
    }
  }
  __syncthreads();

#pragma unroll
  for (int i = 0; i < 3; i++) {               // V -> Vt (aliases K)
    int e = t + i * 256;
    int r = e >> 3, d4 = (e & 7) * 4;
    float4 v4 = *(const float4*)(qkv + (tokbase + (size_t)r * 64) * 768 + 512 + h * 32 + d4);
    VT[(d4 + 0) * 100 + r] = tf32r(v4.x); VT[(d4 + 1) * 100 + r] = tf32r(v4.y);
    VT[(d4 + 2) * 100 + r] = tf32r(v4.z); VT[(d4 + 3) * 100 + r] = tf32r(v4.w);
  }
#pragma unroll
  for (int rr = 0; rr < 6; rr++) {            // softmax 48 rows / 8 warps
    int r = w * 6 + rr;
    float x0 = P[r][lane], x1 = P[r][lane + 32], x2 = P[r][lane + 64];
    float mx = fmaxf(x0, fmaxf(x1, x2));
#pragma unroll
    for (int o = 16; o > 0; o >>= 1) mx = fmaxf(mx, __shfl_xor_sync(0xffffffffu, mx, o));
    float e0 = __expf(x0 - mx), e1 = __expf(x1 - mx), e2 = __expf(x2 - mx);
    float sm = e0 + e1 + e2;
#pragma unroll
    for (int o = 16; o > 0; o >>= 1) sm += __shfl_xor_sync(0xffffffffu, sm, o);
    float inv = 1.f / sm;
    P[r][lane] = tf32r(e0 * inv); P[r][lane + 32] = tf32r(e1 * inv); P[r][lane + 64] = tf32r(e2 * inv);
  }
  __syncthreads();

  if (w < 6) {                                // AV: P(48x96) x Vt(32x96)
    const int wm = w >> 1, wn = w & 1;
    const int m0 = wm * 16;
    float o_[2][4];
#pragma unroll
    for (int jn = 0; jn < 2; jn++)
#pragma unroll
      for (int r = 0; r < 4; r++) o_[jn][r] = 0.f;
#pragma unroll
    for (int ks = 0; ks < 96; ks += 8) {
      unsigned ar[4];
      ar[0] = __float_as_uint(P[m0 + g    ][ks + tq    ]);
      ar[1] = __float_as_uint(P[m0 + g + 8][ks + tq    ]);
      ar[2] = __float_as_uint(P[m0 + g    ][ks + tq + 4]);
      ar[3] = __float_as_uint(P[m0 + g + 8][ks + tq + 4]);
#pragma unroll
      for (int jn = 0; jn < 2; jn++) {
        int n0 = wn * 16 + jn * 8;
        unsigned br[2];
        br[0] = __float_as_uint(VT[(n0 + g) * 100 + ks + tq    ]);
        br[1] = __float_as_uint(VT[(n0 + g) * 100 + ks + tq + 4]);
        mma_tf32(o_[jn], ar, br);
      }
    }
    size_t row0 = tokbase + (size_t)(q0 + m0 + g) * 64;
    size_t row1 = tokbase + (size_t)(q0 + m0 + g + 8) * 64;
#pragma unroll
    for (int jn = 0; jn < 2; jn++) {
      int col = h * 32 + wn * 16 + jn * 8 + 2 * tq;
      *(float2*)&out[row0 * 256 + col] = make_float2(o_[jn][0], o_[jn][1]);
      *(float2*)&out[row1 * 256 + col] = make_float2(o_[jn][2], o_[jn][3]);
    }
  }
}

// ---------------- stage-2 qry attention (mma): per (b2, h): 32 q, 96 keys -------
__global__ __launch_bounds__(256)
void att2_qry_kernel(const float* __restrict__ qkv, const float* __restrict__ kv2,
                     const int* __restrict__ mask, float* __restrict__ out)
{
  __shared__ float Q[32][36], K[96][36], P[32][100];
  __shared__ float kbias[96];
  float* VT = &K[0][0];                 // Vt[d][j] = VT[d*100 + j]
  const int blk = blockIdx.x;
  const int h = blk & 7, b2 = blk >> 3;
  const int b = b2 >> 6, c = b2 & 63;
  const int t = threadIdx.x;
  const size_t tokbase = (size_t)b * 8192 + c;
  const size_t kvbase = (size_t)b2 * 96 * 512 + h * 32;
  const int w = t >> 5, lane = t & 31;
  const int g = lane >> 2, tq = lane & 3;

  {                                           // Q: 32x32 (one f4 per thread)
    int iq = t >> 3, d4 = (t & 7) * 4;
    *(float4*)&Q[iq][d4] = *(const float4*)(qkv + (tokbase + (size_t)(96 + iq) * 64) * 768 + h * 32 + d4);
  }
#pragma unroll
  for (int i = 0; i < 3; i++) {               // K2: 96x32
    int e = t + i * 256;
    int r = e >> 3, d4 = (e & 7) * 4;
    *(float4*)&K[r][d4] = *(const float4*)(kv2 + kvbase + (size_t)r * 512 + d4);
  }
  if (t < 96) kbias[t] = (mask[b * 128 + t] > 0) ? 0.f : -1e9f;
  __syncthreads();
  for (int e = t; e < 96 * 16; e += 256) {    // RoPE K (pos r) via table + round
    int r = e >> 4, i = e & 15;
    float2 t2 = __ldg(&g_rope[e]);
    float ev = K[r][2*i], ov = K[r][2*i+1];
    K[r][2*i] = tf32r(ev * t2.x - ov * t2.y); K[r][2*i+1] = tf32r(ev * t2.y + ov * t2.x);
  }
  for (int e = t; e < 32 * 16; e += 256) {    // RoPE Q (pos 96+iq) via table + round
    int iq = e >> 4, i = e & 15;
    float2 t2 = __ldg(&g_rope[e + 96 * 16]);
    float ev = Q[iq][2*i], ov = Q[iq][2*i+1];
    Q[iq][2*i] = tf32r(ev * t2.x - ov * t2.y); Q[iq][2*i+1] = tf32r(ev * t2.y + ov * t2.x);
  }
  __syncthreads();

  const float scale = 0.17677669529663687f;
  {                                           // scores 32x96: wm = w&1, wn = w>>1
    const int wm = w & 1, wn = w >> 1;
    const int m0 = wm * 16;
    float c_[3][4];
#pragma unroll
    for (int jn = 0; jn < 3; jn++)
#pragma unroll
      for (int r = 0; r < 4; r++) c_[jn][r] = 0.f;
#pragma unroll
    for (int ks = 0; ks < 32; ks += 8) {
      unsigned ar[4];
      ar[0] = __float_as_uint(Q[m0 + g    ][ks + tq    ]);
      ar[1] = __float_as_uint(Q[m0 + g + 8][ks + tq    ]);
      ar[2] = __float_as_uint(Q[m0 + g    ][ks + tq + 4]);
      ar[3] = __float_as_uint(Q[m0 + g + 8][ks + tq + 4]);
#pragma unroll
      for (int jn = 0; jn < 3; jn++) {
        int n0 = wn * 24 + jn * 8;
        unsigned br[2];
        br[0] = __float_as_uint(K[n0 + g][ks + tq    ]);
        br[1] = __float_as_uint(K[n0 + g][ks + tq + 4]);
        mma_tf32(c_[jn], ar, br);
      }
    }
#pragma unroll
    for (int jn = 0; jn < 3; jn++) {
      int col = wn * 24 + jn * 8 + 2 * tq;
      float kb0 = kbias[col], kb1 = kbias[col + 1];
      *(float2*)&P[m0 + g    ][col] = make_float2(c_[jn][0] * scale + kb0, c_[jn][1] * scale + kb1);
      *(float2*)&P[m0 + g + 8][col] = make_float2(c_[jn][2] * scale + kb0, c_[jn][3] * scale + kb1);
    }
  }
  __syncthreads();

#pragma unroll
  for (int i = 0; i < 3; i++) {               // V2 -> Vt (aliases K)
    int e = t + i * 256;
    int r = e >> 3, d4 = (e & 7) * 4;
    float4 v4 = *(const float4*)(kv2 + kvbase + (size_t)r * 512 + 256 + d4);
    VT[(d4 + 0) * 100 + r] = tf32r(v4.x); VT[(d4 + 1) * 100 + r] = tf32r(v4.y);
    VT[(d4 + 2) * 100 + r] = tf32r(v4.z); VT[(d4 + 3) * 100 + r] = tf32r(v4.w);
  }
#pragma unroll
  for (int rr = 0; rr < 4; rr++) {            // softmax 32 rows / 8 warps
    int r = w * 4 + rr;
    float x0 = P[r][lane], x1 = P[r][lane + 32], x2 = P[r][lane + 64];
    float mx = fmaxf(x0, fmaxf(x1, x2));
#pragma unroll
    for (int o = 16; o > 0; o >>= 1) mx = fmaxf(mx, __shfl_xor_sync(0xffffffffu, mx, o));
    float e0 = __expf(x0 - mx), e1 = __expf(x1 - mx), e2 = __expf(x2 - mx);
    float sm = e0 + e1 + e2;
#pragma unroll
    for (int o = 16; o > 0; o >>= 1) sm += __shfl_xor_sync(0xffffffffu, sm, o);
    float inv = 1.f / sm;
    P[r][lane] = tf32r(e0 * inv); P[r][lane + 32] = tf32r(e1 * inv); P[r][lane + 64] = tf32r(e2 * inv);
  }
  __syncthreads();

  {                                           // AV: P(32x96) x Vt(32x96)
    const int wm = w & 1, wn = w >> 1;
    const int m0 = wm * 16;
    const int n0 = wn * 8;
    float o_[4];
#pragma unroll
    for (int r = 0; r < 4; r++) o_[r] = 0.f;
#pragma unroll
    for (int ks = 0; ks < 96; ks += 8) {
      unsigned ar[4], br[2];
      ar[0] = __float_as_uint(P[m0 + g    ][ks + tq    ]);
      ar[1] = __float_as_uint(P[m0 + g + 8][ks + tq    ]);
      ar[2] = __float_as_uint(P[m0 + g    ][ks + tq + 4]);
      ar[3] = __float_as_uint(P[m0 + g + 8][ks + tq + 4]);
      br[0] = __float_as_uint(VT[(n0 + g) * 100 + ks + tq    ]);
      br[1] = __float_as_uint(VT[(n0 + g) * 100 + ks + tq + 4]);
      mma_tf32(o_, ar, br);
    }
    size_t row0 = tokbase + (size_t)(96 + m0 + g) * 64;
    size_t row1 = tokbase + (size_t)(96 + m0 + g + 8) * 64;
    int col = h * 32 + n0 + 2 * tq;
    *(float2*)&out[row0 * 256 + col] = make_float2(o_[0], o_[1]);
    *(float2*)&out[row1 * 256 + col] = make_float2(o_[2], o_[3]);
  }
}

// ---------------- LayerNorm over E=256 (one warp per row) ----------------
__global__ __launch_bounds__(256)
void ln_kernel(const float* __restrict__ x, const float* __restrict__ g,
               const float* __restrict__ bb, float* __restrict__ y)
{
  const int w = threadIdx.x >> 5, lane = threadIdx.x & 31;
  const size_t row = (size_t)blockIdx.x * 8 + w;
  const float* xr = x + row * 256 + lane * 8;
  float4 v0 = *(const float4*)xr;
  float4 v1 = *(const float4*)(xr + 4);
  float s = v0.x+v0.y+v0.z+v0.w + v1.x+v1.y+v1.z+v1.w;
#pragma unroll
  for (int o = 16; o > 0; o >>= 1) s += __shfl_xor_sync(0xffffffffu, s, o);
  float mean = s * 0.00390625f;
  float d0=v0.x-mean, d1=v0.y-mean, d2=v0.z-mean, d3=v0.w-mean;
  float d4=v1.x-mean, d5=v1.y-mean, d6=v1.z-mean, d7=v1.w-mean;
  float q = d0*d0+d1*d1+d2*d2+d3*d3+d4*d4+d5*d5+d6*d6+d7*d7;
#pragma unroll
  for (int o = 16; o > 0; o >>= 1) q += __shfl_xor_sync(0xffffffffu, q, o);
  float rstd = rsqrtf(q * 0.00390625f + 1e-5f);
  const float* gp = g + lane * 8; const float* bp = bb + lane * 8;
  float4 g0 = *(const float4*)gp, g1 = *(const float4*)(gp + 4);
  float4 b0 = *(const float4*)bp, b1 = *(const float4*)(bp + 4);
  float* yr = y + row * 256 + lane * 8;
  *(float4*)yr       = make_float4(d0*rstd*g0.x+b0.x, d1*rstd*g0.y+b0.y,
                                   d2*rstd*g0.z+b0.z, d3*rstd*g0.w+b0.w);
  *(float4*)(yr + 4) = make_float4(d4*rstd*g1.x+b1.x, d5*rstd*g1.y+b1.y,
                                   d6*rstd*g1.z+b1.z, d7*rstd*g1.w+b1.w);
}

// ---------------- launch ----------------
extern "C" void kernel_launch(void* const* d_in, const int* in_sizes, int n_in,
                              void* d_out, int out_size)
{
  const float* src  = (const float*)d_in[0];
  const int*   mask = (const int*)d_in[1];
  int base = (in_sizes[2] == 1) ? 3 : 2;
  const float* y_in_w  = (const float*)d_in[base + 0];
  const float* y_in_b  = (const float*)d_in[base + 1];
  const float* y_out_w = (const float*)d_in[base + 2];
  const float* y_out_b = (const float*)d_in[base + 3];
  const float* x_in_w  = (const float*)d_in[base + 4];
  const float* x_in_b  = (const float*)d_in[base + 5];
  const float* x_out_w = (const float*)d_in[base + 6];
  const float* x_out_b = (const float*)d_in[base + 7];
  const float* w1  = (const float*)d_in[base + 8];
  const float* b1  = (const float*)d_in[base + 9];
  const float* w2  = (const float*)d_in[base + 10];
  const float* b2  = (const float*)d_in[base + 11];
  const float* n1g = (const float*)d_in[base + 12];
  const float* n1b = (const float*)d_in[base + 13];
  const float* n2g = (const float*)d_in[base + 14];
  const float* n2b = (const float*)d_in[base + 15];
  const float* n3g = (const float*)d_in[base + 16];
  const float* n3b = (const float*)d_in[base + 17];
  float* out = (float*)d_out;

  float *x0, *qkvb, *attb, *xnb, *yb, *kv2b, *zb, *hb;
  cudaGetSymbolAddress((void**)&x0,   g_x0);
  cudaGetSymbolAddress((void**)&qkvb, g_qkv);
  cudaGetSymbolAddress((void**)&attb, g_att);
  cudaGetSymbolAddress((void**)&xnb,  g_xn);
  cudaGetSymbolAddress((void**)&yb,   g_y);
  cudaGetSymbolAddress((void**)&kv2b, g_kv2);
  cudaGetSymbolAddress((void**)&zb,   g_z);
  cudaGetSymbolAddress((void**)&hb,   g_h);

  rope_table_kernel<<<8, 256>>>();

  // Stage 1: row-axis self-attention + residual + LN1 (nan_to_num fused into GEMMs)
  gemm_tf32<MAP_ID, MAP_ID, EPI_B,   1, 0><<<dim3(6, 512), 256>>>(src, y_in_w, y_in_b, qkvb, nullptr, 65536, 768, 256);
  att1_kernel<<<8192, 256>>>(qkvb, attb);
  gemm_tf32<MAP_ID, MAP_ID, EPI_RES, 0, 1><<<dim3(2, 512), 256>>>(attb, y_out_w, y_out_b, yb, src, 65536, 256, 256);
  ln_kernel<<<8192, 256>>>(yb, n1g, n1b, xnb);

  // Stage 2: column-axis attention with RoPE + key-padding mask
  gemm_tf32<MAP_ID, MAP_ID, EPI_B,   0, 0><<<dim3(6, 512), 256>>>(xnb, x_in_w, x_in_b, qkvb, nullptr, 65536, 768, 256);
  att2_ctx_kernel<<<8192, 256>>>(qkvb, mask, attb);
  gemm_tf32<MAP_CTX, MAP_CTX, EPI_RES, 0, 0><<<dim3(2, 384), 256>>>(attb, x_out_w, x_out_b, yb, xnb, 49152, 256, 256);
  gemm_tf32<MAP_CTX, MAP_ID,  EPI_B,   0, 0><<<dim3(4, 384), 256>>>(yb, x_in_w + 256 * 256, x_in_b + 256, kv2b, nullptr, 49152, 512, 256);
  att2_qry_kernel<<<4096, 256>>>(qkvb, kv2b, mask, attb);
  gemm_tf32<MAP_QRY, MAP_QRY, EPI_RES, 0, 0><<<dim3(2, 128), 256>>>(attb, x_out_w, x_out_b, yb, xnb, 16384, 256, 256);

  // LN2 + MLP + residual + LN3
  ln_kernel<<<8192, 256>>>(yb, n2g, n2b, zb);
  gemm_tf32<MAP_ID, MAP_ID, EPI_GELU, 0, 0><<<dim3(8, 512), 256>>>(zb, w1, b1, hb, nullptr, 65536, 1024, 256);
  gemm_tf32<MAP_ID, MAP_ID, EPI_RES,  0, 0><<<dim3(2, 512), 256>>>(hb, w2, b2, x0, zb, 65536, 256, 1024);
  ln_kernel<<<8192, 256>>>(x0, n3g, n3b, out);
}